// round 1
// baseline (speedup 1.0000x reference)
#include <cuda_runtime.h>
#include <cstdint>

// Problem constants
#define Hc     2048
#define Mslots 256
#define Bc     8
#define Sc     4096
#define NROWS  (Bc * Sc)      // 32768
#define BR     64             // rows per block (fused kernel)
#define KT     32             // K tile
#define THREADS 256

// smem strides (floats), all keep 16B alignment for float4 LDS
#define XS_STR 68             // x tile, k-major [KT][BR]
#define MS_STR 260            // mem tile, k-major [KT][Mslots]
#define PB_STR 260            // probs [BR][Mslots]
#define VT_STR 132            // mem tile phase2 [32][128]

// dynamic smem: max(phase1 = 32*68 + 32*260 = 10496, phase2 = 64*260 + 32*132 = 20864)
#define SMEM_FLOATS 20864
#define SMEM_BYTES  (SMEM_FLOATS * 4)

// -------- packed f32x2 helpers (FFMA2 path; PTX-only, sm_100+) --------
__device__ __forceinline__ unsigned long long pk2(float lo, float hi) {
    unsigned long long r;
    asm("mov.b64 %0, {%1, %2};" : "=l"(r) : "f"(lo), "f"(hi));
    return r;
}
__device__ __forceinline__ void fma2(unsigned long long& d,
                                     unsigned long long a,
                                     unsigned long long b) {
    asm("fma.rn.f32x2 %0, %1, %2, %0;" : "+l"(d) : "l"(a), "l"(b));
}
__device__ __forceinline__ float2 upk2(unsigned long long v) {
    float2 f;
    asm("mov.b64 {%0, %1}, %2;" : "=f"(f.x), "=f"(f.y) : "l"(v));
    return f;
}

// -------- scratch (__device__ globals: no allocs allowed) --------
#define SCHUNKS 32
__device__ __align__(16) float g_part[SCHUNKS * Bc * Hc];  // partial sums over S
__device__ __align__(16) float g_xmean[Bc * Hc];
__device__ __align__(16) float g_wc[Bc * Hc];

// =====================================================================
// Fused kernel: scores GEMM + softmax + read GEMM + combined assembly
// =====================================================================
__global__ __launch_bounds__(THREADS, 2)
void fused_read_kernel(const float* __restrict__ x,
                       const float* __restrict__ mem,
                       float* __restrict__ comb,
                       float* __restrict__ readm) {
    extern __shared__ float sm[];
    float* xs    = sm;                  // [KT][XS_STR]
    float* ms    = sm + 32 * XS_STR;    // [KT][MS_STR]
    float* probs = sm;                  // [BR][PB_STR]   (reused after sync)
    float* vt    = sm + 64 * PB_STR;    // [32][VT_STR]

    const int tid = threadIdx.x;
    const int tx  = tid & 15;           // col group
    const int ty  = tid >> 4;           // row group
    const int row0 = blockIdx.x * BR;

    // ---------------- Phase 1: scores = x @ mem^T ----------------
    unsigned long long acc[4][8];       // 4 rows x 16 cols (packed pairs)
#pragma unroll
    for (int i = 0; i < 4; i++)
#pragma unroll
        for (int j = 0; j < 8; j++) acc[i][j] = 0ull;

    for (int kt = 0; kt < Hc / KT; ++kt) {
        const int k0 = kt * KT;
        // load x tile [64 x 32] (+ free copy into combined[:, 0:H])
#pragma unroll
        for (int it = 0; it < 2; ++it) {
            int idx = it * 256 + tid;
            int r = idx >> 3, c4 = idx & 7;
            const float4 v = *(const float4*)(x + (size_t)(row0 + r) * Hc + k0 + c4 * 4);
            *(float4*)(comb + (size_t)(row0 + r) * (2 * Hc) + k0 + c4 * 4) = v;
            xs[(c4 * 4 + 0) * XS_STR + r] = v.x;
            xs[(c4 * 4 + 1) * XS_STR + r] = v.y;
            xs[(c4 * 4 + 2) * XS_STR + r] = v.z;
            xs[(c4 * 4 + 3) * XS_STR + r] = v.w;
        }
        // load mem tile [256 x 32], transposed to k-major
#pragma unroll
        for (int it = 0; it < 8; ++it) {
            int idx = it * 256 + tid;
            int m = idx >> 3, c4 = idx & 7;
            const float4 v = *(const float4*)(mem + (size_t)m * Hc + k0 + c4 * 4);
            ms[(c4 * 4 + 0) * MS_STR + m] = v.x;
            ms[(c4 * 4 + 1) * MS_STR + m] = v.y;
            ms[(c4 * 4 + 2) * MS_STR + m] = v.z;
            ms[(c4 * 4 + 3) * MS_STR + m] = v.w;
        }
        __syncthreads();

#pragma unroll
        for (int k = 0; k < KT; ++k) {
            const float4 xv = *(const float4*)&xs[k * XS_STR + ty * 4];
            const float4 m0 = *(const float4*)&ms[k * MS_STR + tx * 16 + 0];
            const float4 m1 = *(const float4*)&ms[k * MS_STR + tx * 16 + 4];
            const float4 m2 = *(const float4*)&ms[k * MS_STR + tx * 16 + 8];
            const float4 m3 = *(const float4*)&ms[k * MS_STR + tx * 16 + 12];
            unsigned long long xb[4] = {pk2(xv.x, xv.x), pk2(xv.y, xv.y),
                                        pk2(xv.z, xv.z), pk2(xv.w, xv.w)};
            unsigned long long mb[8] = {pk2(m0.x, m0.y), pk2(m0.z, m0.w),
                                        pk2(m1.x, m1.y), pk2(m1.z, m1.w),
                                        pk2(m2.x, m2.y), pk2(m2.z, m2.w),
                                        pk2(m3.x, m3.y), pk2(m3.z, m3.w)};
#pragma unroll
            for (int i = 0; i < 4; i++)
#pragma unroll
                for (int j = 0; j < 8; j++) fma2(acc[i][j], xb[i], mb[j]);
        }
        __syncthreads();
    }

    // ---------------- Softmax over M=256 (in registers + shfl) ----------------
    float pr[4][16];
#pragma unroll
    for (int i = 0; i < 4; i++)
#pragma unroll
        for (int j = 0; j < 8; j++) {
            float2 f = upk2(acc[i][j]);
            pr[i][2 * j] = f.x;
            pr[i][2 * j + 1] = f.y;
        }

#pragma unroll
    for (int i = 0; i < 4; i++) {
        float mx = pr[i][0];
#pragma unroll
        for (int j = 1; j < 16; j++) mx = fmaxf(mx, pr[i][j]);
#pragma unroll
        for (int d = 8; d >= 1; d >>= 1)
            mx = fmaxf(mx, __shfl_xor_sync(0xffffffffu, mx, d));
        float s = 0.f;
#pragma unroll
        for (int j = 0; j < 16; j++) {
            pr[i][j] = __expf(pr[i][j] - mx);
            s += pr[i][j];
        }
#pragma unroll
        for (int d = 8; d >= 1; d >>= 1)
            s += __shfl_xor_sync(0xffffffffu, s, d);
        const float inv = 1.f / s;
#pragma unroll
        for (int j = 0; j < 16; j++) pr[i][j] *= inv;
    }

    __syncthreads();  // phase-1 tiles dead; reuse smem for probs
#pragma unroll
    for (int i = 0; i < 4; i++) {
        const int row = ty * 4 + i;
#pragma unroll
        for (int jj = 0; jj < 4; jj++) {
            *(float4*)&probs[row * PB_STR + tx * 16 + jj * 4] =
                make_float4(pr[i][4 * jj], pr[i][4 * jj + 1],
                            pr[i][4 * jj + 2], pr[i][4 * jj + 3]);
        }
    }
    __syncthreads();

    // ---------------- Phase 2: read = probs @ mem ----------------
    for (int hb = 0; hb < 16; ++hb) {
        const int h0 = hb * 128;
        unsigned long long acc2[4][4];
#pragma unroll
        for (int i = 0; i < 4; i++)
#pragma unroll
            for (int j = 0; j < 4; j++) acc2[i][j] = 0ull;

        for (int mt = 0; mt < 8; ++mt) {
#pragma unroll
            for (int it = 0; it < 4; ++it) {
                int idx = it * 256 + tid;
                int mm = idx >> 5, c = idx & 31;
                *(float4*)&vt[mm * VT_STR + c * 4] =
                    *(const float4*)(mem + (size_t)(mt * 32 + mm) * Hc + h0 + c * 4);
            }
            __syncthreads();
#pragma unroll
            for (int mm = 0; mm < 32; ++mm) {
                const float4 v0 = *(const float4*)&vt[mm * VT_STR + tx * 8 + 0];
                const float4 v1 = *(const float4*)&vt[mm * VT_STR + tx * 8 + 4];
                unsigned long long vb[4] = {pk2(v0.x, v0.y), pk2(v0.z, v0.w),
                                            pk2(v1.x, v1.y), pk2(v1.z, v1.w)};
#pragma unroll
                for (int i = 0; i < 4; i++) {
                    const float p = probs[(ty * 4 + i) * PB_STR + mt * 32 + mm];
                    const unsigned long long pb = pk2(p, p);
#pragma unroll
                    for (int j = 0; j < 4; j++) fma2(acc2[i][j], pb, vb[j]);
                }
            }
            __syncthreads();
        }

        // epilogue: write read_memory + combined[:, H + h0 ..]
#pragma unroll
        for (int i = 0; i < 4; i++) {
            const size_t row = (size_t)row0 + ty * 4 + i;
            float2 a0 = upk2(acc2[i][0]), a1 = upk2(acc2[i][1]);
            float2 a2 = upk2(acc2[i][2]), a3 = upk2(acc2[i][3]);
            float4 lo = make_float4(a0.x, a0.y, a1.x, a1.y);
            float4 hi = make_float4(a2.x, a2.y, a3.x, a3.y);
            *(float4*)(readm + row * Hc + h0 + tx * 8 + 0) = lo;
            *(float4*)(readm + row * Hc + h0 + tx * 8 + 4) = hi;
            *(float4*)(comb + row * (2 * Hc) + Hc + h0 + tx * 8 + 0) = lo;
            *(float4*)(comb + row * (2 * Hc) + Hc + h0 + tx * 8 + 4) = hi;
        }
    }
}

// =====================================================================
// Write path
// =====================================================================
__global__ void mean_part_kernel(const float* __restrict__ x) {
    const int sc = blockIdx.x;          // 0..31
    const int b  = blockIdx.y;          // 0..7
    const int tid = threadIdx.x;        // 256
    const int SS = Sc / SCHUNKS;        // 128
    float acc[8] = {0, 0, 0, 0, 0, 0, 0, 0};
    const float* xp = x + ((size_t)b * Sc + (size_t)sc * SS) * Hc;
    for (int s = 0; s < SS; ++s) {
#pragma unroll
        for (int hh = 0; hh < 8; ++hh)
            acc[hh] += xp[(size_t)s * Hc + tid + hh * 256];
    }
#pragma unroll
    for (int hh = 0; hh < 8; ++hh)
        g_part[((size_t)sc * Bc + b) * Hc + tid + hh * 256] = acc[hh];
}

__global__ void mean_reduce_kernel() {
    const int i = blockIdx.x * 256 + threadIdx.x;  // 0..Bc*Hc-1
    float s = 0.f;
#pragma unroll
    for (int sc = 0; sc < SCHUNKS; ++sc) s += g_part[(size_t)sc * Bc * Hc + i];
    g_xmean[i] = s * (1.0f / (float)Sc);
}

__global__ void wc_kernel(const float* __restrict__ W,
                          const float* __restrict__ bw) {
    const int gw = (blockIdx.x * blockDim.x + threadIdx.x) >> 5;
    const int lane = threadIdx.x & 31;
    if (gw >= Bc * Hc) return;
    const int b = gw >> 11;       // / 2048
    const int i = gw & (Hc - 1);
    const float4* wr = (const float4*)(W + (size_t)i * Hc);
    const float4* xm = (const float4*)(g_xmean + (size_t)b * Hc);
    float s = 0.f;
    for (int k = lane; k < Hc / 4; k += 32) {
        float4 w4 = wr[k], x4 = xm[k];
        s += w4.x * x4.x + w4.y * x4.y + w4.z * x4.z + w4.w * x4.w;
    }
#pragma unroll
    for (int d = 16; d >= 1; d >>= 1) s += __shfl_xor_sync(0xffffffffu, s, d);
    if (lane == 0) g_wc[gw] = s + bw[i];
}

__global__ void newmem_kernel(const float* __restrict__ mem,
                              float* __restrict__ outnm) {
    const size_t idx = (size_t)blockIdx.x * 256 + threadIdx.x;  // float4 index
    const int h4 = (int)(idx & (Hc / 4 - 1));
    const size_t rest = idx >> 9;
    const int m = (int)(rest & (Mslots - 1));
    const int b = (int)(rest >> 8);
    float4 mv = *(const float4*)(mem + (size_t)m * Hc + h4 * 4);
    float4 wv = *(const float4*)(g_wc + (size_t)b * Hc + h4 * 4);
    float4 o = make_float4(0.9f * mv.x + 0.1f * wv.x, 0.9f * mv.y + 0.1f * wv.y,
                           0.9f * mv.z + 0.1f * wv.z, 0.9f * mv.w + 0.1f * wv.w);
    ((float4*)outnm)[idx] = o;
}

// =====================================================================
extern "C" void kernel_launch(void* const* d_in, const int* in_sizes, int n_in,
                              void* d_out, int out_size) {
    const float* x   = (const float*)d_in[0];
    const float* mem = (const float*)d_in[1];
    const float* W   = (const float*)d_in[2];
    const float* bw  = (const float*)d_in[3];

    float* comb  = (float*)d_out;                       // [B,S,2H]
    float* readm = comb + (size_t)NROWS * 2 * Hc;       // [B,S,H]
    float* newm  = readm + (size_t)NROWS * Hc;          // [B,M,H]

    cudaFuncSetAttribute(fused_read_kernel,
                         cudaFuncAttributeMaxDynamicSharedMemorySize, SMEM_BYTES);

    fused_read_kernel<<<NROWS / BR, THREADS, SMEM_BYTES>>>(x, mem, comb, readm);

    mean_part_kernel<<<dim3(SCHUNKS, Bc), 256>>>(x);
    mean_reduce_kernel<<<(Bc * Hc) / 256, 256>>>();
    wc_kernel<<<(Bc * Hc * 32) / 256, 256>>>(W, bw);
    newmem_kernel<<<(Bc * Mslots * Hc / 4) / 256, 256>>>(mem, newm);
}

// round 6
// speedup vs baseline: 3.7099x; 3.7099x over previous
#include <cuda_runtime.h>
#include <cuda_bf16.h>
#include <cstdint>

// ---------------- problem constants ----------------
#define Hc      2048
#define Mslots  256
#define Bc      8
#define Sc      4096
#define NROWS   (Bc * Sc)        // 32768
#define BRr     64               // rows per CTA
#define THREADS 256

// ---------------- dynamic smem layout ----------------
// phase 1 (double-buffered k-chunks of 64):
//   XA_HI/XA_LO: x tile   [64 rows x 64 k] bf16, 128B rows, SWZ128
//   MB_HI/MB_LO: mem tile [256 slot x 64 k] bf16, 128B rows, SWZ128
#define XA_HI  0
#define XA_LO  8192
#define MB_HI  16384
#define MB_LO  49152
#define CHUNK  81920
// phase 2 (after phase 1 completes; reuses the same allocation):
//   P_HI/P_LO: probs [64 rows x 256 slot] bf16, 512B rows, SWZ512
//   V_HI/V_LO: memT  [128 h x 256 slot] bf16, 512B rows, SWZ512
#define P_HI   0
#define P_LO   32768
#define V_HI   65536
#define V_LO   131072
#define DSMEM  196608

#define SWZ128(o) ((o) ^ (((o) >> 3) & 0x70))
#define SWZ512(o) ((o) ^ (((o) >> 5) & 0x70))

// ---------------- scratch (__device__ globals) ----------------
__device__ __align__(16) __nv_bfloat16 g_memh[Mslots * Hc];   // mem hi   [slot][k]
__device__ __align__(16) __nv_bfloat16 g_meml[Mslots * Hc];   // mem lo   [slot][k]
__device__ __align__(16) __nv_bfloat16 g_memTh[Hc * Mslots];  // memT hi  [h][slot]
__device__ __align__(16) __nv_bfloat16 g_memTl[Hc * Mslots];  // memT lo  [h][slot]
#define SCHUNKS 32
__device__ __align__(16) float g_part[SCHUNKS * Bc * Hc];
__device__ __align__(16) float g_xmean[Bc * Hc];
__device__ __align__(16) float g_wc[Bc * Hc];

// ---------------- helpers ----------------
__device__ __forceinline__ uint32_t smem_u32(const void* p) {
    uint32_t a;
    asm("{ .reg .u64 t; cvta.to.shared.u64 t, %1; cvt.u32.u64 %0, t; }" : "=r"(a) : "l"(p));
    return a;
}
__device__ __forceinline__ void split2(float a, float b, uint32_t& hw, uint32_t& lw) {
    __nv_bfloat162 h = __floats2bfloat162_rn(a, b);
    float ra = a - __bfloat162float(h.x);
    float rb = b - __bfloat162float(h.y);
    __nv_bfloat162 l = __floats2bfloat162_rn(ra, rb);
    hw = *reinterpret_cast<uint32_t*>(&h);
    lw = *reinterpret_cast<uint32_t*>(&l);
}
__device__ __forceinline__ void ldsm_x4(uint32_t (&r)[4], uint32_t addr) {
    asm volatile("ldmatrix.sync.aligned.m8n8.x4.shared.b16 {%0,%1,%2,%3}, [%4];"
                 : "=r"(r[0]), "=r"(r[1]), "=r"(r[2]), "=r"(r[3]) : "r"(addr));
}
__device__ __forceinline__ void ldsm_x2(uint32_t (&r)[2], uint32_t addr) {
    asm volatile("ldmatrix.sync.aligned.m8n8.x2.shared.b16 {%0,%1}, [%2];"
                 : "=r"(r[0]), "=r"(r[1]) : "r"(addr));
}
__device__ __forceinline__ void mma_bf16(float (&c)[4], const uint32_t (&a)[4],
                                         const uint32_t (&b)[2]) {
    asm volatile(
        "mma.sync.aligned.m16n8k16.row.col.f32.bf16.bf16.f32 "
        "{%0,%1,%2,%3}, {%4,%5,%6,%7}, {%8,%9}, {%0,%1,%2,%3};"
        : "+f"(c[0]), "+f"(c[1]), "+f"(c[2]), "+f"(c[3])
        : "r"(a[0]), "r"(a[1]), "r"(a[2]), "r"(a[3]), "r"(b[0]), "r"(b[1]));
}

// ======================= prep: mem -> bf16 hi/lo (+transpose) =======================
__global__ void prep_mem_kernel(const float* __restrict__ mem) {
    int i = blockIdx.x * 256 + threadIdx.x;          // 0 .. 256*2048-1
    int m = i >> 11, h = i & (Hc - 1);
    float v = mem[i];
    __nv_bfloat16 hi = __float2bfloat16(v);
    __nv_bfloat16 lo = __float2bfloat16(v - __bfloat162float(hi));
    g_memh[i] = hi;                g_meml[i] = lo;
    g_memTh[h * Mslots + m] = hi;  g_memTl[h * Mslots + m] = lo;
}

// ======================= fused HMMA kernel =======================
extern __shared__ __align__(1024) char dsm[];

__global__ __launch_bounds__(THREADS, 1)
void fused_mma_kernel(const float* __restrict__ x,
                      float* __restrict__ comb,
                      float* __restrict__ readm) {
    __shared__ float s_red[4][64];

    const int tid = threadIdx.x;
    const int lane = tid & 31;
    const int wid = tid >> 5;
    const int wm = wid >> 2;             // 0..1 (M position)
    const int wn = wid & 3;              // 0..3 (N position)
    const int row0 = blockIdx.x * BRr;
    const uint32_t sb = smem_u32(dsm);

    // ---------------- phase 1: scores = x @ mem^T ----------------
    float acc[2][8][4];
#pragma unroll
    for (int mf = 0; mf < 2; ++mf)
#pragma unroll
        for (int nf = 0; nf < 8; ++nf)
#pragma unroll
            for (int e = 0; e < 4; ++e) acc[mf][nf][e] = 0.f;

    // --- stage chunk 0 ---
    {
        const int k0 = 0;
        char* buf = dsm;
#pragma unroll
        for (int it = 0; it < 4; ++it) {
            int idx = it * 256 + tid;
            int r = idx >> 4, c4 = idx & 15;
            float4 v = *(const float4*)(x + (size_t)(row0 + r) * Hc + k0 + c4 * 4);
            *(float4*)(comb + (size_t)(row0 + r) * (2 * Hc) + k0 + c4 * 4) = v;
            uint32_t h0w, l0w, h1w, l1w;
            split2(v.x, v.y, h0w, l0w);
            split2(v.z, v.w, h1w, l1w);
            uint32_t off = SWZ128((uint32_t)(r * 128 + c4 * 8));
            *(uint2*)(buf + XA_HI + off) = make_uint2(h0w, h1w);
            *(uint2*)(buf + XA_LO + off) = make_uint2(l0w, l1w);
        }
#pragma unroll
        for (int it = 0; it < 8; ++it) {
            int idx = it * 256 + tid;
            int m = idx >> 3, c8 = idx & 7;
            uint32_t off = SWZ128((uint32_t)(m * 128 + c8 * 16));
            *(uint4*)(buf + MB_HI + off) = *(const uint4*)(g_memh + (size_t)m * Hc + k0 + c8 * 8);
            *(uint4*)(buf + MB_LO + off) = *(const uint4*)(g_meml + (size_t)m * Hc + k0 + c8 * 8);
        }
    }
    __syncthreads();

    for (int t = 0; t < 32; ++t) {
        // --- stage chunk t+1 into the other buffer (no sync needed yet) ---
        if (t < 31) {
            const int k0 = (t + 1) * 64;
            char* buf = dsm + (size_t)((t + 1) & 1) * CHUNK;
#pragma unroll
            for (int it = 0; it < 4; ++it) {
                int idx = it * 256 + tid;
                int r = idx >> 4, c4 = idx & 15;
                float4 v = *(const float4*)(x + (size_t)(row0 + r) * Hc + k0 + c4 * 4);
                *(float4*)(comb + (size_t)(row0 + r) * (2 * Hc) + k0 + c4 * 4) = v;
                uint32_t h0w, l0w, h1w, l1w;
                split2(v.x, v.y, h0w, l0w);
                split2(v.z, v.w, h1w, l1w);
                uint32_t off = SWZ128((uint32_t)(r * 128 + c4 * 8));
                *(uint2*)(buf + XA_HI + off) = make_uint2(h0w, h1w);
                *(uint2*)(buf + XA_LO + off) = make_uint2(l0w, l1w);
            }
#pragma unroll
            for (int it = 0; it < 8; ++it) {
                int idx = it * 256 + tid;
                int m = idx >> 3, c8 = idx & 7;
                uint32_t off = SWZ128((uint32_t)(m * 128 + c8 * 16));
                *(uint4*)(buf + MB_HI + off) = *(const uint4*)(g_memh + (size_t)m * Hc + k0 + c8 * 8);
                *(uint4*)(buf + MB_LO + off) = *(const uint4*)(g_meml + (size_t)m * Hc + k0 + c8 * 8);
            }
        }
        // --- compute chunk t ---
        const uint32_t bo = sb + (uint32_t)(t & 1) * CHUNK;
#pragma unroll
        for (int ks = 0; ks < 4; ++ks) {
            const uint32_t kb = (uint32_t)ks * 32;
            uint32_t ah[2][4], al[2][4];
#pragma unroll
            for (int mf = 0; mf < 2; ++mf) {
                int row = wm * 32 + mf * 16 + (lane & 15);
                uint32_t ao = SWZ128((uint32_t)(row * 128) + kb + ((uint32_t)(lane >> 4) << 4));
                ldsm_x4(ah[mf], bo + XA_HI + ao);
                ldsm_x4(al[mf], bo + XA_LO + ao);
            }
#pragma unroll
            for (int nf = 0; nf < 8; ++nf) {
                int slot = wn * 64 + nf * 8 + (lane & 7);
                uint32_t bofs = SWZ128((uint32_t)(slot * 128) + kb +
                                       ((uint32_t)((lane >> 3) & 1) << 4));
                uint32_t bh[2], bl[2];
                ldsm_x2(bh, bo + MB_HI + bofs);
                ldsm_x2(bl, bo + MB_LO + bofs);
#pragma unroll
                for (int mf = 0; mf < 2; ++mf) {
                    mma_bf16(acc[mf][nf], ah[mf], bh);
                    mma_bf16(acc[mf][nf], ah[mf], bl);
                    mma_bf16(acc[mf][nf], al[mf], bh);
                }
            }
        }
        __syncthreads();
    }

    // ---------------- softmax over M=256 (cross-warp via s_red) ----------------
    float rmax[2][2], rsum[2][2], inv[2][2];
#pragma unroll
    for (int mf = 0; mf < 2; ++mf)
#pragma unroll
        for (int rh = 0; rh < 2; ++rh) {
            float m = -3.4e38f;
#pragma unroll
            for (int nf = 0; nf < 8; ++nf) {
                m = fmaxf(m, acc[mf][nf][rh * 2]);
                m = fmaxf(m, acc[mf][nf][rh * 2 + 1]);
            }
            m = fmaxf(m, __shfl_xor_sync(0xffffffffu, m, 1));
            m = fmaxf(m, __shfl_xor_sync(0xffffffffu, m, 2));
            rmax[mf][rh] = m;
        }
    if ((lane & 3) == 0) {
#pragma unroll
        for (int mf = 0; mf < 2; ++mf)
#pragma unroll
            for (int rh = 0; rh < 2; ++rh)
                s_red[wn][wm * 32 + mf * 16 + (lane >> 2) + rh * 8] = rmax[mf][rh];
    }
    __syncthreads();
#pragma unroll
    for (int mf = 0; mf < 2; ++mf)
#pragma unroll
        for (int rh = 0; rh < 2; ++rh) {
            int row = wm * 32 + mf * 16 + (lane >> 2) + rh * 8;
            float m = s_red[0][row];
            m = fmaxf(m, s_red[1][row]);
            m = fmaxf(m, s_red[2][row]);
            m = fmaxf(m, s_red[3][row]);
            rmax[mf][rh] = m;
            rsum[mf][rh] = 0.f;
        }
    __syncthreads();
#pragma unroll
    for (int mf = 0; mf < 2; ++mf)
#pragma unroll
        for (int nf = 0; nf < 8; ++nf)
#pragma unroll
            for (int rh = 0; rh < 2; ++rh) {
                float e0 = __expf(acc[mf][nf][rh * 2]     - rmax[mf][rh]);
                float e1 = __expf(acc[mf][nf][rh * 2 + 1] - rmax[mf][rh]);
                acc[mf][nf][rh * 2]     = e0;
                acc[mf][nf][rh * 2 + 1] = e1;
                rsum[mf][rh] += e0 + e1;
            }
#pragma unroll
    for (int mf = 0; mf < 2; ++mf)
#pragma unroll
        for (int rh = 0; rh < 2; ++rh) {
            float s = rsum[mf][rh];
            s += __shfl_xor_sync(0xffffffffu, s, 1);
            s += __shfl_xor_sync(0xffffffffu, s, 2);
            rsum[mf][rh] = s;
        }
    if ((lane & 3) == 0) {
#pragma unroll
        for (int mf = 0; mf < 2; ++mf)
#pragma unroll
            for (int rh = 0; rh < 2; ++rh)
                s_red[wn][wm * 32 + mf * 16 + (lane >> 2) + rh * 8] = rsum[mf][rh];
    }
    __syncthreads();
#pragma unroll
    for (int mf = 0; mf < 2; ++mf)
#pragma unroll
        for (int rh = 0; rh < 2; ++rh) {
            int row = wm * 32 + mf * 16 + (lane >> 2) + rh * 8;
            inv[mf][rh] = 1.0f / (s_red[0][row] + s_red[1][row] +
                                  s_red[2][row] + s_red[3][row]);
        }
    __syncthreads();

    // ---------------- store P (unnormalized exp) hi/lo to smem ----------------
#pragma unroll
    for (int mf = 0; mf < 2; ++mf)
#pragma unroll
        for (int rh = 0; rh < 2; ++rh) {
            int rloc = wm * 32 + mf * 16 + (lane >> 2) + rh * 8;
#pragma unroll
            for (int nf = 0; nf < 8; ++nf) {
                int col = wn * 64 + nf * 8 + (lane & 3) * 2;
                uint32_t ph, pl;
                split2(acc[mf][nf][rh * 2], acc[mf][nf][rh * 2 + 1], ph, pl);
                uint32_t off = SWZ512((uint32_t)(rloc * 512 + col * 2));
                *(uint32_t*)(dsm + P_HI + off) = ph;
                *(uint32_t*)(dsm + P_LO + off) = pl;
            }
        }
    __syncthreads();

    // ---------------- phase 2: read = P @ mem ----------------
    for (int ht = 0; ht < 16; ++ht) {
        const int h0 = ht * 128;
        // load V tiles [128 h x 256 slot] hi/lo from g_memT*
#pragma unroll
        for (int it = 0; it < 16; ++it) {
            int idx = it * 256 + tid;
            int r = idx >> 5, c16 = idx & 31;
            uint32_t soff = SWZ512((uint32_t)(r * 512 + c16 * 16));
            *(uint4*)(dsm + V_HI + soff) =
                *(const uint4*)(g_memTh + (size_t)(h0 + r) * Mslots + c16 * 8);
            *(uint4*)(dsm + V_LO + soff) =
                *(const uint4*)(g_memTl + (size_t)(h0 + r) * Mslots + c16 * 8);
        }
        __syncthreads();

        float o[2][4][4];
#pragma unroll
        for (int mf = 0; mf < 2; ++mf)
#pragma unroll
            for (int nf = 0; nf < 4; ++nf)
#pragma unroll
                for (int e = 0; e < 4; ++e) o[mf][nf][e] = 0.f;

#pragma unroll
        for (int ks = 0; ks < 16; ++ks) {
            const uint32_t kb = (uint32_t)ks * 32;
            uint32_t ph_[2][4], pl_[2][4];
#pragma unroll
            for (int mf = 0; mf < 2; ++mf) {
                int row = wm * 32 + mf * 16 + (lane & 15);
                uint32_t ao = SWZ512((uint32_t)(row * 512) + kb + ((uint32_t)(lane >> 4) << 4));
                ldsm_x4(ph_[mf], sb + P_HI + ao);
                ldsm_x4(pl_[mf], sb + P_LO + ao);
            }
#pragma unroll
            for (int nf = 0; nf < 4; ++nf) {
                int hrow = wn * 32 + nf * 8 + (lane & 7);
                uint32_t bofs = SWZ512((uint32_t)(hrow * 512) + kb +
                                       ((uint32_t)((lane >> 3) & 1) << 4));
                uint32_t vh[2], vl[2];
                ldsm_x2(vh, sb + V_HI + bofs);
                ldsm_x2(vl, sb + V_LO + bofs);
#pragma unroll
                for (int mf = 0; mf < 2; ++mf) {
                    mma_bf16(o[mf][nf], ph_[mf], vh);
                    mma_bf16(o[mf][nf], ph_[mf], vl);
                    mma_bf16(o[mf][nf], pl_[mf], vh);
                }
            }
        }

        // epilogue: scale by 1/sum, write readm + combined[:, H+...]
#pragma unroll
        for (int mf = 0; mf < 2; ++mf)
#pragma unroll
            for (int rh = 0; rh < 2; ++rh) {
                const size_t row = (size_t)row0 + wm * 32 + mf * 16 + (lane >> 2) + rh * 8;
                const float iv = inv[mf][rh];
#pragma unroll
                for (int nf = 0; nf < 4; ++nf) {
                    int h = h0 + wn * 32 + nf * 8 + (lane & 3) * 2;
                    float2 v = make_float2(o[mf][nf][rh * 2] * iv,
                                           o[mf][nf][rh * 2 + 1] * iv);
                    *(float2*)(readm + row * Hc + h) = v;
                    *(float2*)(comb + row * (2 * Hc) + Hc + h) = v;
                }
            }
        __syncthreads();
    }
}

// ======================= write path =======================
__global__ void mean_part_kernel(const float* __restrict__ x) {
    const int sc = blockIdx.x, b = blockIdx.y, tid = threadIdx.x;
    const int SS = Sc / SCHUNKS;
    float acc[8] = {0, 0, 0, 0, 0, 0, 0, 0};
    const float* xp = x + ((size_t)b * Sc + (size_t)sc * SS) * Hc;
    for (int s = 0; s < SS; ++s) {
#pragma unroll
        for (int hh = 0; hh < 8; ++hh)
            acc[hh] += xp[(size_t)s * Hc + tid + hh * 256];
    }
#pragma unroll
    for (int hh = 0; hh < 8; ++hh)
        g_part[((size_t)sc * Bc + b) * Hc + tid + hh * 256] = acc[hh];
}

__global__ void mean_reduce_kernel() {
    const int i = blockIdx.x * 256 + threadIdx.x;
    float s = 0.f;
#pragma unroll
    for (int sc = 0; sc < SCHUNKS; ++sc) s += g_part[(size_t)sc * Bc * Hc + i];
    g_xmean[i] = s * (1.0f / (float)Sc);
}

__global__ void wc_kernel(const float* __restrict__ W, const float* __restrict__ bw) {
    const int gw = (blockIdx.x * blockDim.x + threadIdx.x) >> 5;
    const int lane = threadIdx.x & 31;
    if (gw >= Bc * Hc) return;
    const int b = gw >> 11, i = gw & (Hc - 1);
    const float4* wr = (const float4*)(W + (size_t)i * Hc);
    const float4* xm = (const float4*)(g_xmean + (size_t)b * Hc);
    float s = 0.f;
    for (int k = lane; k < Hc / 4; k += 32) {
        float4 w4 = wr[k], x4 = xm[k];
        s += w4.x * x4.x + w4.y * x4.y + w4.z * x4.z + w4.w * x4.w;
    }
#pragma unroll
    for (int d = 16; d >= 1; d >>= 1) s += __shfl_xor_sync(0xffffffffu, s, d);
    if (lane == 0) g_wc[gw] = s + bw[i];
}

__global__ void newmem_kernel(const float* __restrict__ mem, float* __restrict__ outnm) {
    const size_t idx = (size_t)blockIdx.x * 256 + threadIdx.x;
    const int h4 = (int)(idx & (Hc / 4 - 1));
    const size_t rest = idx >> 9;
    const int m = (int)(rest & (Mslots - 1));
    const int b = (int)(rest >> 8);
    float4 mv = *(const float4*)(mem + (size_t)m * Hc + h4 * 4);
    float4 wv = *(const float4*)(g_wc + (size_t)b * Hc + h4 * 4);
    ((float4*)outnm)[idx] = make_float4(0.9f * mv.x + 0.1f * wv.x, 0.9f * mv.y + 0.1f * wv.y,
                                        0.9f * mv.z + 0.1f * wv.z, 0.9f * mv.w + 0.1f * wv.w);
}

// ======================= launch =======================
extern "C" void kernel_launch(void* const* d_in, const int* in_sizes, int n_in,
                              void* d_out, int out_size) {
    const float* x   = (const float*)d_in[0];
    const float* mem = (const float*)d_in[1];
    const float* W   = (const float*)d_in[2];
    const float* bw  = (const float*)d_in[3];

    float* comb  = (float*)d_out;
    float* readm = comb + (size_t)NROWS * 2 * Hc;
    float* newm  = readm + (size_t)NROWS * Hc;

    cudaFuncSetAttribute(fused_mma_kernel,
                         cudaFuncAttributeMaxDynamicSharedMemorySize, DSMEM);

    // write path first; fused kernel is launch #6 so the ncu -s 5 -c 1
    // window captures it.
    prep_mem_kernel<<<(Mslots * Hc) / 256, 256>>>(mem);
    mean_part_kernel<<<dim3(SCHUNKS, Bc), 256>>>(x);
    mean_reduce_kernel<<<(Bc * Hc) / 256, 256>>>();
    wc_kernel<<<(Bc * Hc * 32) / 256, 256>>>(W, bw);
    newmem_kernel<<<(Bc * Mslots * Hc / 4) / 256, 256>>>(mem, newm);
    fused_mma_kernel<<<NROWS / BRr, THREADS, DSMEM>>>(x, comb, readm);
}

// round 7
// speedup vs baseline: 3.7746x; 1.0175x over previous
#include <cuda_runtime.h>
#include <cuda_bf16.h>
#include <cstdint>

// ---------------- problem constants ----------------
#define Hc      2048
#define Mslots  256
#define Bc      8
#define Sc      4096
#define NROWS   (Bc * Sc)        // 32768
#define BRr     64               // rows per CTA
#define THREADS 512              // 16 warps (4 per SMSP) for latency hiding

// ---------------- dynamic smem layout ----------------
#define XA_HI  0
#define XA_LO  8192
#define MB_HI  16384
#define MB_LO  49152
#define CHUNK  81920
#define P_HI   0
#define P_LO   32768
#define V_HI   65536
#define V_LO   131072
#define DSMEM  196608

#define SWZ128(o) ((o) ^ (((o) >> 3) & 0x70))
#define SWZ512(o) ((o) ^ (((o) >> 5) & 0x70))

// ---------------- scratch (__device__ globals) ----------------
__device__ __align__(16) __nv_bfloat16 g_memh[Mslots * Hc];   // mem hi   [slot][k]
__device__ __align__(16) __nv_bfloat16 g_meml[Mslots * Hc];   // mem lo   [slot][k]
__device__ __align__(16) __nv_bfloat16 g_memTh[Hc * Mslots];  // memT hi  [h][slot]
__device__ __align__(16) __nv_bfloat16 g_memTl[Hc * Mslots];  // memT lo  [h][slot]
#define SCHUNKS 32
__device__ __align__(16) float g_part[SCHUNKS * Bc * Hc];
__device__ __align__(16) float g_xmean[Bc * Hc];
__device__ __align__(16) float g_wc[Bc * Hc];

// ---------------- helpers ----------------
__device__ __forceinline__ uint32_t smem_u32(const void* p) {
    uint32_t a;
    asm("{ .reg .u64 t; cvta.to.shared.u64 t, %1; cvt.u32.u64 %0, t; }" : "=r"(a) : "l"(p));
    return a;
}
__device__ __forceinline__ void split2(float a, float b, uint32_t& hw, uint32_t& lw) {
    __nv_bfloat162 h = __floats2bfloat162_rn(a, b);
    float ra = a - __bfloat162float(h.x);
    float rb = b - __bfloat162float(h.y);
    __nv_bfloat162 l = __floats2bfloat162_rn(ra, rb);
    hw = *reinterpret_cast<uint32_t*>(&h);
    lw = *reinterpret_cast<uint32_t*>(&l);
}
__device__ __forceinline__ void ldsm_x4(uint32_t (&r)[4], uint32_t addr) {
    asm volatile("ldmatrix.sync.aligned.m8n8.x4.shared.b16 {%0,%1,%2,%3}, [%4];"
                 : "=r"(r[0]), "=r"(r[1]), "=r"(r[2]), "=r"(r[3]) : "r"(addr));
}
__device__ __forceinline__ void ldsm_x2(uint32_t (&r)[2], uint32_t addr) {
    asm volatile("ldmatrix.sync.aligned.m8n8.x2.shared.b16 {%0,%1}, [%2];"
                 : "=r"(r[0]), "=r"(r[1]) : "r"(addr));
}
__device__ __forceinline__ void mma_bf16(float (&c)[4], const uint32_t (&a)[4],
                                         const uint32_t (&b)[2]) {
    asm volatile(
        "mma.sync.aligned.m16n8k16.row.col.f32.bf16.bf16.f32 "
        "{%0,%1,%2,%3}, {%4,%5,%6,%7}, {%8,%9}, {%0,%1,%2,%3};"
        : "+f"(c[0]), "+f"(c[1]), "+f"(c[2]), "+f"(c[3])
        : "r"(a[0]), "r"(a[1]), "r"(a[2]), "r"(a[3]), "r"(b[0]), "r"(b[1]));
}

// ======================= prep: mem -> bf16 hi/lo (+transpose) =======================
__global__ void prep_mem_kernel(const float* __restrict__ mem) {
    int i = blockIdx.x * 256 + threadIdx.x;
    int m = i >> 11, h = i & (Hc - 1);
    float v = mem[i];
    __nv_bfloat16 hi = __float2bfloat16(v);
    __nv_bfloat16 lo = __float2bfloat16(v - __bfloat162float(hi));
    g_memh[i] = hi;                g_meml[i] = lo;
    g_memTh[h * Mslots + m] = hi;  g_memTl[h * Mslots + m] = lo;
}

// ======================= fused HMMA kernel =======================
extern __shared__ __align__(1024) char dsm[];

__global__ __launch_bounds__(THREADS, 1)
void fused_mma_kernel(const float* __restrict__ x,
                      float* __restrict__ comb,
                      float* __restrict__ readm) {
    __shared__ float s_red[8][64];

    const int tid = threadIdx.x;
    const int lane = tid & 31;
    const int wid = tid >> 5;
    const int wm = wid >> 3;             // 0..1 (M position)
    const int wn = wid & 7;              // 0..7 (N position)
    const int row0 = blockIdx.x * BRr;
    const uint32_t sb = smem_u32(dsm);

    // ---------------- phase 1: scores = x @ mem^T ----------------
    float acc[2][4][4];
#pragma unroll
    for (int mf = 0; mf < 2; ++mf)
#pragma unroll
        for (int nf = 0; nf < 4; ++nf)
#pragma unroll
            for (int e = 0; e < 4; ++e) acc[mf][nf][e] = 0.f;

    // --- stage chunk 0 ---
    {
        char* buf = dsm;
#pragma unroll
        for (int it = 0; it < 2; ++it) {
            int idx = it * 512 + tid;
            int r = idx >> 4, c4 = idx & 15;
            float4 v = *(const float4*)(x + (size_t)(row0 + r) * Hc + c4 * 4);
            *(float4*)(comb + (size_t)(row0 + r) * (2 * Hc) + c4 * 4) = v;
            uint32_t h0w, l0w, h1w, l1w;
            split2(v.x, v.y, h0w, l0w);
            split2(v.z, v.w, h1w, l1w);
            uint32_t off = SWZ128((uint32_t)(r * 128 + c4 * 8));
            *(uint2*)(buf + XA_HI + off) = make_uint2(h0w, h1w);
            *(uint2*)(buf + XA_LO + off) = make_uint2(l0w, l1w);
        }
#pragma unroll
        for (int it = 0; it < 4; ++it) {
            int idx = it * 512 + tid;
            int m = idx >> 3, c8 = idx & 7;
            uint32_t off = SWZ128((uint32_t)(m * 128 + c8 * 16));
            *(uint4*)(buf + MB_HI + off) = *(const uint4*)(g_memh + (size_t)m * Hc + c8 * 8);
            *(uint4*)(buf + MB_LO + off) = *(const uint4*)(g_meml + (size_t)m * Hc + c8 * 8);
        }
    }
    __syncthreads();

    for (int t = 0; t < 32; ++t) {
        // --- stage chunk t+1 into the other buffer ---
        if (t < 31) {
            const int k0 = (t + 1) * 64;
            char* buf = dsm + (size_t)((t + 1) & 1) * CHUNK;
#pragma unroll
            for (int it = 0; it < 2; ++it) {
                int idx = it * 512 + tid;
                int r = idx >> 4, c4 = idx & 15;
                float4 v = *(const float4*)(x + (size_t)(row0 + r) * Hc + k0 + c4 * 4);
                *(float4*)(comb + (size_t)(row0 + r) * (2 * Hc) + k0 + c4 * 4) = v;
                uint32_t h0w, l0w, h1w, l1w;
                split2(v.x, v.y, h0w, l0w);
                split2(v.z, v.w, h1w, l1w);
                uint32_t off = SWZ128((uint32_t)(r * 128 + c4 * 8));
                *(uint2*)(buf + XA_HI + off) = make_uint2(h0w, h1w);
                *(uint2*)(buf + XA_LO + off) = make_uint2(l0w, l1w);
            }
#pragma unroll
            for (int it = 0; it < 4; ++it) {
                int idx = it * 512 + tid;
                int m = idx >> 3, c8 = idx & 7;
                uint32_t off = SWZ128((uint32_t)(m * 128 + c8 * 16));
                *(uint4*)(buf + MB_HI + off) = *(const uint4*)(g_memh + (size_t)m * Hc + k0 + c8 * 8);
                *(uint4*)(buf + MB_LO + off) = *(const uint4*)(g_meml + (size_t)m * Hc + k0 + c8 * 8);
            }
        }
        // --- compute chunk t ---
        const uint32_t bo = sb + (uint32_t)(t & 1) * CHUNK;
#pragma unroll
        for (int ks = 0; ks < 4; ++ks) {
            const uint32_t kb = (uint32_t)ks * 32;
            uint32_t ah[2][4], al[2][4];
#pragma unroll
            for (int mf = 0; mf < 2; ++mf) {
                int row = wm * 32 + mf * 16 + (lane & 15);
                uint32_t ao = SWZ128((uint32_t)(row * 128) + kb + ((uint32_t)(lane >> 4) << 4));
                ldsm_x4(ah[mf], bo + XA_HI + ao);
                ldsm_x4(al[mf], bo + XA_LO + ao);
            }
#pragma unroll
            for (int nf = 0; nf < 4; ++nf) {
                int slot = wn * 32 + nf * 8 + (lane & 7);
                uint32_t bofs = SWZ128((uint32_t)(slot * 128) + kb +
                                       ((uint32_t)((lane >> 3) & 1) << 4));
                uint32_t bh[2], bl[2];
                ldsm_x2(bh, bo + MB_HI + bofs);
                ldsm_x2(bl, bo + MB_LO + bofs);
#pragma unroll
                for (int mf = 0; mf < 2; ++mf) {
                    mma_bf16(acc[mf][nf], ah[mf], bh);
                    mma_bf16(acc[mf][nf], ah[mf], bl);
                    mma_bf16(acc[mf][nf], al[mf], bh);
                }
            }
        }
        __syncthreads();
    }

    // ---------------- softmax over M=256 (cross-warp via s_red) ----------------
    float rmax[2][2], rsum[2][2], inv[2][2];
#pragma unroll
    for (int mf = 0; mf < 2; ++mf)
#pragma unroll
        for (int rh = 0; rh < 2; ++rh) {
            float m = -3.4e38f;
#pragma unroll
            for (int nf = 0; nf < 4; ++nf) {
                m = fmaxf(m, acc[mf][nf][rh * 2]);
                m = fmaxf(m, acc[mf][nf][rh * 2 + 1]);
            }
            m = fmaxf(m, __shfl_xor_sync(0xffffffffu, m, 1));
            m = fmaxf(m, __shfl_xor_sync(0xffffffffu, m, 2));
            rmax[mf][rh] = m;
        }
    if ((lane & 3) == 0) {
#pragma unroll
        for (int mf = 0; mf < 2; ++mf)
#pragma unroll
            for (int rh = 0; rh < 2; ++rh)
                s_red[wn][wm * 32 + mf * 16 + (lane >> 2) + rh * 8] = rmax[mf][rh];
    }
    __syncthreads();
#pragma unroll
    for (int mf = 0; mf < 2; ++mf)
#pragma unroll
        for (int rh = 0; rh < 2; ++rh) {
            int row = wm * 32 + mf * 16 + (lane >> 2) + rh * 8;
            float m = s_red[0][row];
#pragma unroll
            for (int j = 1; j < 8; ++j) m = fmaxf(m, s_red[j][row]);
            rmax[mf][rh] = m;
            rsum[mf][rh] = 0.f;
        }
    __syncthreads();
#pragma unroll
    for (int mf = 0; mf < 2; ++mf)
#pragma unroll
        for (int nf = 0; nf < 4; ++nf)
#pragma unroll
            for (int rh = 0; rh < 2; ++rh) {
                float e0 = __expf(acc[mf][nf][rh * 2]     - rmax[mf][rh]);
                float e1 = __expf(acc[mf][nf][rh * 2 + 1] - rmax[mf][rh]);
                acc[mf][nf][rh * 2]     = e0;
                acc[mf][nf][rh * 2 + 1] = e1;
                rsum[mf][rh] += e0 + e1;
            }
#pragma unroll
    for (int mf = 0; mf < 2; ++mf)
#pragma unroll
        for (int rh = 0; rh < 2; ++rh) {
            float s = rsum[mf][rh];
            s += __shfl_xor_sync(0xffffffffu, s, 1);
            s += __shfl_xor_sync(0xffffffffu, s, 2);
            rsum[mf][rh] = s;
        }
    if ((lane & 3) == 0) {
#pragma unroll
        for (int mf = 0; mf < 2; ++mf)
#pragma unroll
            for (int rh = 0; rh < 2; ++rh)
                s_red[wn][wm * 32 + mf * 16 + (lane >> 2) + rh * 8] = rsum[mf][rh];
    }
    __syncthreads();
#pragma unroll
    for (int mf = 0; mf < 2; ++mf)
#pragma unroll
        for (int rh = 0; rh < 2; ++rh) {
            int row = wm * 32 + mf * 16 + (lane >> 2) + rh * 8;
            float s = s_red[0][row];
#pragma unroll
            for (int j = 1; j < 8; ++j) s += s_red[j][row];
            inv[mf][rh] = 1.0f / s;
        }
    __syncthreads();

    // ---------------- store P (unnormalized exp) hi/lo to smem ----------------
#pragma unroll
    for (int mf = 0; mf < 2; ++mf)
#pragma unroll
        for (int rh = 0; rh < 2; ++rh) {
            int rloc = wm * 32 + mf * 16 + (lane >> 2) + rh * 8;
#pragma unroll
            for (int nf = 0; nf < 4; ++nf) {
                int col = wn * 32 + nf * 8 + (lane & 3) * 2;
                uint32_t ph, pl;
                split2(acc[mf][nf][rh * 2], acc[mf][nf][rh * 2 + 1], ph, pl);
                uint32_t off = SWZ512((uint32_t)(rloc * 512 + col * 2));
                *(uint32_t*)(dsm + P_HI + off) = ph;
                *(uint32_t*)(dsm + P_LO + off) = pl;
            }
        }
    __syncthreads();

    // ---------------- phase 2: read = P @ mem ----------------
    for (int ht = 0; ht < 16; ++ht) {
        const int h0 = ht * 128;
#pragma unroll
        for (int it = 0; it < 8; ++it) {
            int idx = it * 512 + tid;
            int r = idx >> 5, c16 = idx & 31;
            uint32_t soff = SWZ512((uint32_t)(r * 512 + c16 * 16));
            *(uint4*)(dsm + V_HI + soff) =
                *(const uint4*)(g_memTh + (size_t)(h0 + r) * Mslots + c16 * 8);
            *(uint4*)(dsm + V_LO + soff) =
                *(const uint4*)(g_memTl + (size_t)(h0 + r) * Mslots + c16 * 8);
        }
        __syncthreads();

        float o[2][2][4];
#pragma unroll
        for (int mf = 0; mf < 2; ++mf)
#pragma unroll
            for (int nf = 0; nf < 2; ++nf)
#pragma unroll
                for (int e = 0; e < 4; ++e) o[mf][nf][e] = 0.f;

#pragma unroll
        for (int ks = 0; ks < 16; ++ks) {
            const uint32_t kb = (uint32_t)ks * 32;
            uint32_t ph_[2][4], pl_[2][4];
#pragma unroll
            for (int mf = 0; mf < 2; ++mf) {
                int row = wm * 32 + mf * 16 + (lane & 15);
                uint32_t ao = SWZ512((uint32_t)(row * 512) + kb + ((uint32_t)(lane >> 4) << 4));
                ldsm_x4(ph_[mf], sb + P_HI + ao);
                ldsm_x4(pl_[mf], sb + P_LO + ao);
            }
#pragma unroll
            for (int nf = 0; nf < 2; ++nf) {
                int hrow = wn * 16 + nf * 8 + (lane & 7);
                uint32_t bofs = SWZ512((uint32_t)(hrow * 512) + kb +
                                       ((uint32_t)((lane >> 3) & 1) << 4));
                uint32_t vh[2], vl[2];
                ldsm_x2(vh, sb + V_HI + bofs);
                ldsm_x2(vl, sb + V_LO + bofs);
#pragma unroll
                for (int mf = 0; mf < 2; ++mf) {
                    mma_bf16(o[mf][nf], ph_[mf], vh);
                    mma_bf16(o[mf][nf], ph_[mf], vl);
                    mma_bf16(o[mf][nf], pl_[mf], vh);
                }
            }
        }

        // epilogue: scale by 1/sum, write readm + combined[:, H+...]
#pragma unroll
        for (int mf = 0; mf < 2; ++mf)
#pragma unroll
            for (int rh = 0; rh < 2; ++rh) {
                const size_t row = (size_t)row0 + wm * 32 + mf * 16 + (lane >> 2) + rh * 8;
                const float iv = inv[mf][rh];
#pragma unroll
                for (int nf = 0; nf < 2; ++nf) {
                    int h = h0 + wn * 16 + nf * 8 + (lane & 3) * 2;
                    float2 v = make_float2(o[mf][nf][rh * 2] * iv,
                                           o[mf][nf][rh * 2 + 1] * iv);
                    *(float2*)(readm + row * Hc + h) = v;
                    *(float2*)(comb + row * (2 * Hc) + Hc + h) = v;
                }
            }
        __syncthreads();
    }
}

// ======================= write path =======================
__global__ void mean_part_kernel(const float* __restrict__ x) {
    const int sc = blockIdx.x, b = blockIdx.y, tid = threadIdx.x;
    const int SS = Sc / SCHUNKS;
    float acc[8] = {0, 0, 0, 0, 0, 0, 0, 0};
    const float* xp = x + ((size_t)b * Sc + (size_t)sc * SS) * Hc;
    for (int s = 0; s < SS; ++s) {
#pragma unroll
        for (int hh = 0; hh < 8; ++hh)
            acc[hh] += xp[(size_t)s * Hc + tid + hh * 256];
    }
#pragma unroll
    for (int hh = 0; hh < 8; ++hh)
        g_part[((size_t)sc * Bc + b) * Hc + tid + hh * 256] = acc[hh];
}

__global__ void mean_reduce_kernel() {
    const int i = blockIdx.x * 256 + threadIdx.x;
    float s = 0.f;
#pragma unroll
    for (int sc = 0; sc < SCHUNKS; ++sc) s += g_part[(size_t)sc * Bc * Hc + i];
    g_xmean[i] = s * (1.0f / (float)Sc);
}

__global__ void wc_kernel(const float* __restrict__ W, const float* __restrict__ bw) {
    const int gw = (blockIdx.x * blockDim.x + threadIdx.x) >> 5;
    const int lane = threadIdx.x & 31;
    if (gw >= Bc * Hc) return;
    const int b = gw >> 11, i = gw & (Hc - 1);
    const float4* wr = (const float4*)(W + (size_t)i * Hc);
    const float4* xm = (const float4*)(g_xmean + (size_t)b * Hc);
    float s = 0.f;
    for (int k = lane; k < Hc / 4; k += 32) {
        float4 w4 = wr[k], x4 = xm[k];
        s += w4.x * x4.x + w4.y * x4.y + w4.z * x4.z + w4.w * x4.w;
    }
#pragma unroll
    for (int d = 16; d >= 1; d >>= 1) s += __shfl_xor_sync(0xffffffffu, s, d);
    if (lane == 0) g_wc[gw] = s + bw[i];
}

__global__ void newmem_kernel(const float* __restrict__ mem, float* __restrict__ outnm) {
    const size_t idx = (size_t)blockIdx.x * 256 + threadIdx.x;
    const int h4 = (int)(idx & (Hc / 4 - 1));
    const size_t rest = idx >> 9;
    const int m = (int)(rest & (Mslots - 1));
    const int b = (int)(rest >> 8);
    float4 mv = *(const float4*)(mem + (size_t)m * Hc + h4 * 4);
    float4 wv = *(const float4*)(g_wc + (size_t)b * Hc + h4 * 4);
    ((float4*)outnm)[idx] = make_float4(0.9f * mv.x + 0.1f * wv.x, 0.9f * mv.y + 0.1f * wv.y,
                                        0.9f * mv.z + 0.1f * wv.z, 0.9f * mv.w + 0.1f * wv.w);
}

// ======================= launch =======================
extern "C" void kernel_launch(void* const* d_in, const int* in_sizes, int n_in,
                              void* d_out, int out_size) {
    const float* x   = (const float*)d_in[0];
    const float* mem = (const float*)d_in[1];
    const float* W   = (const float*)d_in[2];
    const float* bw  = (const float*)d_in[3];

    float* comb  = (float*)d_out;
    float* readm = comb + (size_t)NROWS * 2 * Hc;
    float* newm  = readm + (size_t)NROWS * Hc;

    cudaFuncSetAttribute(fused_mma_kernel,
                         cudaFuncAttributeMaxDynamicSharedMemorySize, DSMEM);

    prep_mem_kernel<<<(Mslots * Hc) / 256, 256>>>(mem);
    mean_part_kernel<<<dim3(SCHUNKS, Bc), 256>>>(x);
    mean_reduce_kernel<<<(Bc * Hc) / 256, 256>>>();
    wc_kernel<<<(Bc * Hc * 32) / 256, 256>>>(W, bw);
    newmem_kernel<<<(Bc * Mslots * Hc / 4) / 256, 256>>>(mem, newm);
    fused_mma_kernel<<<NROWS / BRr, THREADS, DSMEM>>>(x, comb, readm);
}

// round 9
// speedup vs baseline: 4.3848x; 1.1617x over previous
#include <cuda_runtime.h>
#include <cuda_bf16.h>
#include <cuda_fp16.h>
#include <cstdint>

// ---------------- problem constants ----------------
#define Hc      2048
#define Mslots  256
#define Bc      8
#define Sc      4096
#define NROWS   (Bc * Sc)        // 32768
#define BRr     64               // rows per CTA
#define THREADS 256              // 8 warps; 2 CTAs/SM via smem diet

// ---------------- dynamic smem layout (96KB total) ----------------
// phase 1 (single-buffered k-chunks of 64):
#define XA_HI  0                 // x hi  [64 x 64k]  8KB
#define XA_LO  8192              // x lo              8KB
#define MB_HI  16384             // mem hi [256 x 64k] 32KB
#define MB_LO  49152             // mem lo            32KB  (end 80KB)
// phase 2 (reuses allocation):
#define P_F16  0                 // P fp16 [64 x 256] 32KB
#define V_HI   32768             // memT hi fp16 [64h x 256] 32KB
#define V_LO   65536             // memT lo fp16              32KB (end 96KB)
#define DSMEM  98304

#define SWZ128(o) ((o) ^ (((o) >> 3) & 0x70))
#define SWZ512(o) ((o) ^ (((o) >> 5) & 0x70))

// ---------------- scratch (__device__ globals) ----------------
__device__ __align__(16) __nv_bfloat16 g_memh[Mslots * Hc];   // mem hi  bf16 [slot][k]
__device__ __align__(16) __nv_bfloat16 g_meml[Mslots * Hc];   // mem lo  bf16 [slot][k]
__device__ __align__(16) __half        g_memTh[Hc * Mslots];  // memT hi fp16 [h][slot]
__device__ __align__(16) __half        g_memTl[Hc * Mslots];  // memT lo fp16 [h][slot]
#define SCHUNKS 32
__device__ __align__(16) float g_part[SCHUNKS * Bc * Hc];
__device__ __align__(16) float g_xmean[Bc * Hc];
__device__ __align__(16) float g_wc[Bc * Hc];

// ---------------- helpers ----------------
__device__ __forceinline__ uint32_t smem_u32(const void* p) {
    uint32_t a;
    asm("{ .reg .u64 t; cvta.to.shared.u64 t, %1; cvt.u32.u64 %0, t; }" : "=r"(a) : "l"(p));
    return a;
}
__device__ __forceinline__ void split2(float a, float b, uint32_t& hw, uint32_t& lw) {
    __nv_bfloat162 h = __floats2bfloat162_rn(a, b);
    float ra = a - __bfloat162float(h.x);
    float rb = b - __bfloat162float(h.y);
    __nv_bfloat162 l = __floats2bfloat162_rn(ra, rb);
    hw = *reinterpret_cast<uint32_t*>(&h);
    lw = *reinterpret_cast<uint32_t*>(&l);
}
__device__ __forceinline__ void ldsm_x4(uint32_t (&r)[4], uint32_t addr) {
    asm volatile("ldmatrix.sync.aligned.m8n8.x4.shared.b16 {%0,%1,%2,%3}, [%4];"
                 : "=r"(r[0]), "=r"(r[1]), "=r"(r[2]), "=r"(r[3]) : "r"(addr));
}
__device__ __forceinline__ void ldsm_x2(uint32_t (&r)[2], uint32_t addr) {
    asm volatile("ldmatrix.sync.aligned.m8n8.x2.shared.b16 {%0,%1}, [%2];"
                 : "=r"(r[0]), "=r"(r[1]) : "r"(addr));
}
__device__ __forceinline__ void mma_bf16(float (&c)[4], const uint32_t (&a)[4],
                                         const uint32_t (&b)[2]) {
    asm volatile(
        "mma.sync.aligned.m16n8k16.row.col.f32.bf16.bf16.f32 "
        "{%0,%1,%2,%3}, {%4,%5,%6,%7}, {%8,%9}, {%0,%1,%2,%3};"
        : "+f"(c[0]), "+f"(c[1]), "+f"(c[2]), "+f"(c[3])
        : "r"(a[0]), "r"(a[1]), "r"(a[2]), "r"(a[3]), "r"(b[0]), "r"(b[1]));
}
__device__ __forceinline__ void mma_f16(float (&c)[4], const uint32_t (&a)[4],
                                        const uint32_t (&b)[2]) {
    asm volatile(
        "mma.sync.aligned.m16n8k16.row.col.f32.f16.f16.f32 "
        "{%0,%1,%2,%3}, {%4,%5,%6,%7}, {%8,%9}, {%0,%1,%2,%3};"
        : "+f"(c[0]), "+f"(c[1]), "+f"(c[2]), "+f"(c[3])
        : "r"(a[0]), "r"(a[1]), "r"(a[2]), "r"(a[3]), "r"(b[0]), "r"(b[1]));
}

// ======================= prep: mem -> bf16 hi/lo + fp16 hi/lo transpose =======================
__global__ void prep_mem_kernel(const float* __restrict__ mem) {
    int i = blockIdx.x * 256 + threadIdx.x;
    int m = i >> 11, h = i & (Hc - 1);
    float v = mem[i];
    __nv_bfloat16 bh = __float2bfloat16(v);
    __nv_bfloat16 bl = __float2bfloat16(v - __bfloat162float(bh));
    g_memh[i] = bh;
    g_meml[i] = bl;
    __half hh = __float2half_rn(v);
    __half hl = __float2half_rn(v - __half2float(hh));
    g_memTh[h * Mslots + m] = hh;
    g_memTl[h * Mslots + m] = hl;
}

// ======================= fused HMMA kernel =======================
extern __shared__ __align__(1024) char dsm[];

__global__ __launch_bounds__(THREADS, 2)
void fused_mma_kernel(const float* __restrict__ x,
                      float* __restrict__ comb,
                      float* __restrict__ readm) {
    __shared__ float s_red[4][64];

    const int tid = threadIdx.x;
    const int lane = tid & 31;
    const int wid = tid >> 5;
    const int wm = wid >> 2;             // 0..1 (M position)
    const int wn = wid & 3;              // 0..3 (N position)
    const int row0 = blockIdx.x * BRr;
    const uint32_t sb = smem_u32(dsm);

    // ---------------- phase 1: scores = x @ mem^T (bf16, 3-product) ----------------
    float acc[2][8][4];
#pragma unroll
    for (int mf = 0; mf < 2; ++mf)
#pragma unroll
        for (int nf = 0; nf < 8; ++nf)
#pragma unroll
            for (int e = 0; e < 4; ++e) acc[mf][nf][e] = 0.f;

    for (int t = 0; t < 32; ++t) {
        const int k0 = t * 64;
        // stage chunk t (single buffer; co-resident CTA hides latency)
#pragma unroll
        for (int it = 0; it < 4; ++it) {
            int idx = it * 256 + tid;
            int r = idx >> 4, c4 = idx & 15;
            float4 v = *(const float4*)(x + (size_t)(row0 + r) * Hc + k0 + c4 * 4);
            *(float4*)(comb + (size_t)(row0 + r) * (2 * Hc) + k0 + c4 * 4) = v;
            uint32_t h0w, l0w, h1w, l1w;
            split2(v.x, v.y, h0w, l0w);
            split2(v.z, v.w, h1w, l1w);
            uint32_t off = SWZ128((uint32_t)(r * 128 + c4 * 8));
            *(uint2*)(dsm + XA_HI + off) = make_uint2(h0w, h1w);
            *(uint2*)(dsm + XA_LO + off) = make_uint2(l0w, l1w);
        }
#pragma unroll
        for (int it = 0; it < 8; ++it) {
            int idx = it * 256 + tid;
            int m = idx >> 3, c8 = idx & 7;
            uint32_t off = SWZ128((uint32_t)(m * 128 + c8 * 16));
            *(uint4*)(dsm + MB_HI + off) = *(const uint4*)(g_memh + (size_t)m * Hc + k0 + c8 * 8);
            *(uint4*)(dsm + MB_LO + off) = *(const uint4*)(g_meml + (size_t)m * Hc + k0 + c8 * 8);
        }
        __syncthreads();
        // compute chunk t
#pragma unroll
        for (int ks = 0; ks < 4; ++ks) {
            const uint32_t kb = (uint32_t)ks * 32;
            uint32_t ah[2][4], al[2][4];
#pragma unroll
            for (int mf = 0; mf < 2; ++mf) {
                int row = wm * 32 + mf * 16 + (lane & 15);
                uint32_t ao = SWZ128((uint32_t)(row * 128) + kb + ((uint32_t)(lane >> 4) << 4));
                ldsm_x4(ah[mf], sb + XA_HI + ao);
                ldsm_x4(al[mf], sb + XA_LO + ao);
            }
#pragma unroll
            for (int nf = 0; nf < 8; ++nf) {
                int slot = wn * 64 + nf * 8 + (lane & 7);
                uint32_t bofs = SWZ128((uint32_t)(slot * 128) + kb +
                                       ((uint32_t)((lane >> 3) & 1) << 4));
                uint32_t bh[2], bl[2];
                ldsm_x2(bh, sb + MB_HI + bofs);
                ldsm_x2(bl, sb + MB_LO + bofs);
#pragma unroll
                for (int mf = 0; mf < 2; ++mf) {
                    mma_bf16(acc[mf][nf], ah[mf], bh);
                    mma_bf16(acc[mf][nf], ah[mf], bl);
                    mma_bf16(acc[mf][nf], al[mf], bh);
                }
            }
        }
        __syncthreads();
    }

    // ---------------- softmax over M=256 (cross-warp via s_red) ----------------
    float rmax[2][2], rsum[2][2], inv[2][2];
#pragma unroll
    for (int mf = 0; mf < 2; ++mf)
#pragma unroll
        for (int rh = 0; rh < 2; ++rh) {
            float m = -3.4e38f;
#pragma unroll
            for (int nf = 0; nf < 8; ++nf) {
                m = fmaxf(m, acc[mf][nf][rh * 2]);
                m = fmaxf(m, acc[mf][nf][rh * 2 + 1]);
            }
            m = fmaxf(m, __shfl_xor_sync(0xffffffffu, m, 1));
            m = fmaxf(m, __shfl_xor_sync(0xffffffffu, m, 2));
            rmax[mf][rh] = m;
        }
    if ((lane & 3) == 0) {
#pragma unroll
        for (int mf = 0; mf < 2; ++mf)
#pragma unroll
            for (int rh = 0; rh < 2; ++rh)
                s_red[wn][wm * 32 + mf * 16 + (lane >> 2) + rh * 8] = rmax[mf][rh];
    }
    __syncthreads();
#pragma unroll
    for (int mf = 0; mf < 2; ++mf)
#pragma unroll
        for (int rh = 0; rh < 2; ++rh) {
            int row = wm * 32 + mf * 16 + (lane >> 2) + rh * 8;
            float m = s_red[0][row];
            m = fmaxf(m, s_red[1][row]);
            m = fmaxf(m, s_red[2][row]);
            m = fmaxf(m, s_red[3][row]);
            rmax[mf][rh] = m;
            rsum[mf][rh] = 0.f;
        }
    __syncthreads();
#pragma unroll
    for (int mf = 0; mf < 2; ++mf)
#pragma unroll
        for (int nf = 0; nf < 8; ++nf)
#pragma unroll
            for (int rh = 0; rh < 2; ++rh) {
                float e0 = __expf(acc[mf][nf][rh * 2]     - rmax[mf][rh]);
                float e1 = __expf(acc[mf][nf][rh * 2 + 1] - rmax[mf][rh]);
                acc[mf][nf][rh * 2]     = e0;
                acc[mf][nf][rh * 2 + 1] = e1;
                rsum[mf][rh] += e0 + e1;
            }
#pragma unroll
    for (int mf = 0; mf < 2; ++mf)
#pragma unroll
        for (int rh = 0; rh < 2; ++rh) {
            float s = rsum[mf][rh];
            s += __shfl_xor_sync(0xffffffffu, s, 1);
            s += __shfl_xor_sync(0xffffffffu, s, 2);
            rsum[mf][rh] = s;
        }
    if ((lane & 3) == 0) {
#pragma unroll
        for (int mf = 0; mf < 2; ++mf)
#pragma unroll
            for (int rh = 0; rh < 2; ++rh)
                s_red[wn][wm * 32 + mf * 16 + (lane >> 2) + rh * 8] = rsum[mf][rh];
    }
    __syncthreads();
#pragma unroll
    for (int mf = 0; mf < 2; ++mf)
#pragma unroll
        for (int rh = 0; rh < 2; ++rh) {
            int row = wm * 32 + mf * 16 + (lane >> 2) + rh * 8;
            inv[mf][rh] = 1.0f / (s_red[0][row] + s_red[1][row] +
                                  s_red[2][row] + s_red[3][row]);
        }
    __syncthreads();

    // ---------------- store P (unnormalized exp) as fp16 to smem ----------------
#pragma unroll
    for (int mf = 0; mf < 2; ++mf)
#pragma unroll
        for (int rh = 0; rh < 2; ++rh) {
            int rloc = wm * 32 + mf * 16 + (lane >> 2) + rh * 8;
#pragma unroll
            for (int nf = 0; nf < 8; ++nf) {
                int col = wn * 64 + nf * 8 + (lane & 3) * 2;
                __half2 pv = __floats2half2_rn(acc[mf][nf][rh * 2],
                                               acc[mf][nf][rh * 2 + 1]);
                uint32_t off = SWZ512((uint32_t)(rloc * 512 + col * 2));
                *(uint32_t*)(dsm + P_F16 + off) = *reinterpret_cast<uint32_t*>(&pv);
            }
        }
    __syncthreads();

    // ---------------- phase 2: read = P @ mem (fp16, 2-product) ----------------
    for (int ht = 0; ht < 32; ++ht) {
        const int h0 = ht * 64;
        // stage V tile [64 h x 256 slot] fp16 hi/lo
        // NOTE: each 16-byte unit gets its OWN swizzled offset (SWZ512 does not
        // commute with +16 when mask bit 4 is set — round-8 bug).
#pragma unroll
        for (int it = 0; it < 4; ++it) {
            int idx = it * 256 + tid;
            int r = idx >> 4, c16 = idx & 15;
            uint32_t o = (uint32_t)(r * 512 + c16 * 32);
            uint32_t s0 = SWZ512(o);
            uint32_t s1 = SWZ512(o + 16);
            const __half* srch = g_memTh + (size_t)(h0 + r) * Mslots + c16 * 16;
            const __half* srcl = g_memTl + (size_t)(h0 + r) * Mslots + c16 * 16;
            *(uint4*)(dsm + V_HI + s0) = *(const uint4*)(srch);
            *(uint4*)(dsm + V_HI + s1) = *(const uint4*)(srch + 8);
            *(uint4*)(dsm + V_LO + s0) = *(const uint4*)(srcl);
            *(uint4*)(dsm + V_LO + s1) = *(const uint4*)(srcl + 8);
        }
        __syncthreads();

        float o2[2][2][4];
#pragma unroll
        for (int mf = 0; mf < 2; ++mf)
#pragma unroll
            for (int nf = 0; nf < 2; ++nf)
#pragma unroll
                for (int e = 0; e < 4; ++e) o2[mf][nf][e] = 0.f;

#pragma unroll
        for (int ks = 0; ks < 16; ++ks) {
            const uint32_t kb = (uint32_t)ks * 32;
            uint32_t pf[2][4];
#pragma unroll
            for (int mf = 0; mf < 2; ++mf) {
                int row = wm * 32 + mf * 16 + (lane & 15);
                uint32_t ao = SWZ512((uint32_t)(row * 512) + kb + ((uint32_t)(lane >> 4) << 4));
                ldsm_x4(pf[mf], sb + P_F16 + ao);
            }
#pragma unroll
            for (int nf = 0; nf < 2; ++nf) {
                int hrow = wn * 16 + nf * 8 + (lane & 7);
                uint32_t bofs = SWZ512((uint32_t)(hrow * 512) + kb +
                                       ((uint32_t)((lane >> 3) & 1) << 4));
                uint32_t vh[2], vl[2];
                ldsm_x2(vh, sb + V_HI + bofs);
                ldsm_x2(vl, sb + V_LO + bofs);
#pragma unroll
                for (int mf = 0; mf < 2; ++mf) {
                    mma_f16(o2[mf][nf], pf[mf], vh);
                    mma_f16(o2[mf][nf], pf[mf], vl);
                }
            }
        }

        // epilogue: scale by 1/sum, write readm + combined[:, H+...]
#pragma unroll
        for (int mf = 0; mf < 2; ++mf)
#pragma unroll
            for (int rh = 0; rh < 2; ++rh) {
                const size_t row = (size_t)row0 + wm * 32 + mf * 16 + (lane >> 2) + rh * 8;
                const float iv = inv[mf][rh];
#pragma unroll
                for (int nf = 0; nf < 2; ++nf) {
                    int h = h0 + wn * 16 + nf * 8 + (lane & 3) * 2;
                    float2 v = make_float2(o2[mf][nf][rh * 2] * iv,
                                           o2[mf][nf][rh * 2 + 1] * iv);
                    *(float2*)(readm + row * Hc + h) = v;
                    *(float2*)(comb + row * (2 * Hc) + Hc + h) = v;
                }
            }
        __syncthreads();
    }
}

// ======================= write path =======================
__global__ void mean_part_kernel(const float* __restrict__ x) {
    const int sc = blockIdx.x, b = blockIdx.y, tid = threadIdx.x;
    const int SS = Sc / SCHUNKS;
    float acc[8] = {0, 0, 0, 0, 0, 0, 0, 0};
    const float* xp = x + ((size_t)b * Sc + (size_t)sc * SS) * Hc;
    for (int s = 0; s < SS; ++s) {
#pragma unroll
        for (int hh = 0; hh < 8; ++hh)
            acc[hh] += xp[(size_t)s * Hc + tid + hh * 256];
    }
#pragma unroll
    for (int hh = 0; hh < 8; ++hh)
        g_part[((size_t)sc * Bc + b) * Hc + tid + hh * 256] = acc[hh];
}

__global__ void mean_reduce_kernel() {
    const int i = blockIdx.x * 256 + threadIdx.x;
    float s = 0.f;
#pragma unroll
    for (int sc = 0; sc < SCHUNKS; ++sc) s += g_part[(size_t)sc * Bc * Hc + i];
    g_xmean[i] = s * (1.0f / (float)Sc);
}

__global__ void wc_kernel(const float* __restrict__ W, const float* __restrict__ bw) {
    const int gw = (blockIdx.x * blockDim.x + threadIdx.x) >> 5;
    const int lane = threadIdx.x & 31;
    if (gw >= Bc * Hc) return;
    const int b = gw >> 11, i = gw & (Hc - 1);
    const float4* wr = (const float4*)(W + (size_t)i * Hc);
    const float4* xm = (const float4*)(g_xmean + (size_t)b * Hc);
    float s = 0.f;
    for (int k = lane; k < Hc / 4; k += 32) {
        float4 w4 = wr[k], x4 = xm[k];
        s += w4.x * x4.x + w4.y * x4.y + w4.z * x4.z + w4.w * x4.w;
    }
#pragma unroll
    for (int d = 16; d >= 1; d >>= 1) s += __shfl_xor_sync(0xffffffffu, s, d);
    if (lane == 0) g_wc[gw] = s + bw[i];
}

__global__ void newmem_kernel(const float* __restrict__ mem, float* __restrict__ outnm) {
    const size_t idx = (size_t)blockIdx.x * 256 + threadIdx.x;
    const int h4 = (int)(idx & (Hc / 4 - 1));
    const size_t rest = idx >> 9;
    const int m = (int)(rest & (Mslots - 1));
    const int b = (int)(rest >> 8);
    float4 mv = *(const float4*)(mem + (size_t)m * Hc + h4 * 4);
    float4 wv = *(const float4*)(g_wc + (size_t)b * Hc + h4 * 4);
    ((float4*)outnm)[idx] = make_float4(0.9f * mv.x + 0.1f * wv.x, 0.9f * mv.y + 0.1f * wv.y,
                                        0.9f * mv.z + 0.1f * wv.z, 0.9f * mv.w + 0.1f * wv.w);
}

// ======================= launch =======================
extern "C" void kernel_launch(void* const* d_in, const int* in_sizes, int n_in,
                              void* d_out, int out_size) {
    const float* x   = (const float*)d_in[0];
    const float* mem = (const float*)d_in[1];
    const float* W   = (const float*)d_in[2];
    const float* bw  = (const float*)d_in[3];

    float* comb  = (float*)d_out;
    float* readm = comb + (size_t)NROWS * 2 * Hc;
    float* newm  = readm + (size_t)NROWS * Hc;

    cudaFuncSetAttribute(fused_mma_kernel,
                         cudaFuncAttributeMaxDynamicSharedMemorySize, DSMEM);

    prep_mem_kernel<<<(Mslots * Hc) / 256, 256>>>(mem);
    mean_part_kernel<<<dim3(SCHUNKS, Bc), 256>>>(x);
    mean_reduce_kernel<<<(Bc * Hc) / 256, 256>>>();
    wc_kernel<<<(Bc * Hc * 32) / 256, 256>>>(W, bw);
    newmem_kernel<<<(Bc * Mslots * Hc / 4) / 256, 256>>>(mem, newm);
    fused_mma_kernel<<<NROWS / BRr, THREADS, DSMEM>>>(x, comb, readm);
}

// round 10
// speedup vs baseline: 5.6403x; 1.2863x over previous
#include <cuda_runtime.h>
#include <cuda_bf16.h>
#include <cuda_fp16.h>
#include <cstdint>

// ---------------- problem constants ----------------
#define Hc      2048
#define Mslots  256
#define Bc      8
#define Sc      4096
#define NROWS   (Bc * Sc)        // 32768
#define BRr     64               // rows per CTA
#define THREADS 256              // 8 warps; 2 CTAs/SM

// ---------------- dynamic smem layout (96KB) ----------------
// phase 1 (single-buffered k-chunks of 64):
#define XA_HI  0                 // x hi  [64 x 64k]  8KB
#define XA_LO  8192              // x lo              8KB
#define MB_HI  16384             // mem hi [256 x 64k] 32KB
#define MB_LO  49152             // mem lo            32KB  (end 80KB)
// phase 2 (reuses allocation):
#define P_F16  0                 // P fp16 [64 x 256]        32KB
#define V_F16  32768             // memT fp16 [128h x 256]   64KB (end 96KB)
#define DSMEM  98304

#define SWZ128(o) ((o) ^ (((o) >> 3) & 0x70))
#define SWZ512(o) ((o) ^ (((o) >> 5) & 0x70))

// ---------------- scratch (__device__ globals) ----------------
__device__ __align__(16) __nv_bfloat16 g_memh[Mslots * Hc];   // mem hi  bf16 [slot][k]
__device__ __align__(16) __nv_bfloat16 g_meml[Mslots * Hc];   // mem lo  bf16 [slot][k]
__device__ __align__(16) __half        g_memT[Hc * Mslots];   // memT fp16 [h][slot]
#define SCHUNKS 32
__device__ __align__(16) float g_part[SCHUNKS * Bc * Hc];
__device__ __align__(16) float g_xmean[Bc * Hc];
__device__ __align__(16) float g_wc[Bc * Hc];

// ---------------- helpers ----------------
__device__ __forceinline__ uint32_t smem_u32(const void* p) {
    uint32_t a;
    asm("{ .reg .u64 t; cvta.to.shared.u64 t, %1; cvt.u32.u64 %0, t; }" : "=r"(a) : "l"(p));
    return a;
}
__device__ __forceinline__ void split2(float a, float b, uint32_t& hw, uint32_t& lw) {
    __nv_bfloat162 h = __floats2bfloat162_rn(a, b);
    float ra = a - __bfloat162float(h.x);
    float rb = b - __bfloat162float(h.y);
    __nv_bfloat162 l = __floats2bfloat162_rn(ra, rb);
    hw = *reinterpret_cast<uint32_t*>(&h);
    lw = *reinterpret_cast<uint32_t*>(&l);
}
__device__ __forceinline__ void ldsm_x4(uint32_t (&r)[4], uint32_t addr) {
    asm volatile("ldmatrix.sync.aligned.m8n8.x4.shared.b16 {%0,%1,%2,%3}, [%4];"
                 : "=r"(r[0]), "=r"(r[1]), "=r"(r[2]), "=r"(r[3]) : "r"(addr));
}
__device__ __forceinline__ void mma_bf16(float (&c)[4], const uint32_t (&a)[4],
                                         uint32_t b0, uint32_t b1) {
    asm volatile(
        "mma.sync.aligned.m16n8k16.row.col.f32.bf16.bf16.f32 "
        "{%0,%1,%2,%3}, {%4,%5,%6,%7}, {%8,%9}, {%0,%1,%2,%3};"
        : "+f"(c[0]), "+f"(c[1]), "+f"(c[2]), "+f"(c[3])
        : "r"(a[0]), "r"(a[1]), "r"(a[2]), "r"(a[3]), "r"(b0), "r"(b1));
}
__device__ __forceinline__ void mma_f16(float (&c)[4], const uint32_t (&a)[4],
                                        uint32_t b0, uint32_t b1) {
    asm volatile(
        "mma.sync.aligned.m16n8k16.row.col.f32.f16.f16.f32 "
        "{%0,%1,%2,%3}, {%4,%5,%6,%7}, {%8,%9}, {%0,%1,%2,%3};"
        : "+f"(c[0]), "+f"(c[1]), "+f"(c[2]), "+f"(c[3])
        : "r"(a[0]), "r"(a[1]), "r"(a[2]), "r"(a[3]), "r"(b0), "r"(b1));
}

// ======================= prep: mem -> bf16 hi/lo + fp16 transpose =======================
__global__ void prep_mem_kernel(const float* __restrict__ mem) {
    int i = blockIdx.x * 256 + threadIdx.x;
    int m = i >> 11, h = i & (Hc - 1);
    float v = mem[i];
    __nv_bfloat16 bh = __float2bfloat16(v);
    __nv_bfloat16 bl = __float2bfloat16(v - __bfloat162float(bh));
    g_memh[i] = bh;
    g_meml[i] = bl;
    g_memT[h * Mslots + m] = __float2half_rn(v);
}

// ======================= fused HMMA kernel =======================
extern __shared__ __align__(1024) char dsm[];

__global__ __launch_bounds__(THREADS, 2)
void fused_mma_kernel(const float* __restrict__ x,
                      float* __restrict__ comb,
                      float* __restrict__ readm) {
    __shared__ float s_red[4][64];

    const int tid = threadIdx.x;
    const int lane = tid & 31;
    const int wid = tid >> 5;
    const int wm = wid >> 2;             // 0..1 (M position)
    const int wn = wid & 3;              // 0..3 (N position)
    const int row0 = blockIdx.x * BRr;
    const uint32_t sb = smem_u32(dsm);
    // lane decomposition for paired (x4) B loads
    const int b_nfp = (lane >> 4) & 1;   // which nf of the pair
    const int b_kh  = (lane >> 3) & 1;   // which k-half
    const int b_row = lane & 7;

    // ---------------- phase 1: scores = x @ mem^T (bf16, 3-product) ----------------
    float acc[2][8][4];
#pragma unroll
    for (int mf = 0; mf < 2; ++mf)
#pragma unroll
        for (int nf = 0; nf < 8; ++nf)
#pragma unroll
            for (int e = 0; e < 4; ++e) acc[mf][nf][e] = 0.f;

    for (int t = 0; t < 32; ++t) {
        const int k0 = t * 64;
        // stage chunk t (single buffer; co-resident CTA hides latency)
#pragma unroll
        for (int it = 0; it < 4; ++it) {
            int idx = it * 256 + tid;
            int r = idx >> 4, c4 = idx & 15;
            float4 v = *(const float4*)(x + (size_t)(row0 + r) * Hc + k0 + c4 * 4);
            *(float4*)(comb + (size_t)(row0 + r) * (2 * Hc) + k0 + c4 * 4) = v;
            uint32_t h0w, l0w, h1w, l1w;
            split2(v.x, v.y, h0w, l0w);
            split2(v.z, v.w, h1w, l1w);
            uint32_t off = SWZ128((uint32_t)(r * 128 + c4 * 8));
            *(uint2*)(dsm + XA_HI + off) = make_uint2(h0w, h1w);
            *(uint2*)(dsm + XA_LO + off) = make_uint2(l0w, l1w);
        }
#pragma unroll
        for (int it = 0; it < 8; ++it) {
            int idx = it * 256 + tid;
            int m = idx >> 3, c8 = idx & 7;
            uint32_t off = SWZ128((uint32_t)(m * 128 + c8 * 16));
            *(uint4*)(dsm + MB_HI + off) = *(const uint4*)(g_memh + (size_t)m * Hc + k0 + c8 * 8);
            *(uint4*)(dsm + MB_LO + off) = *(const uint4*)(g_meml + (size_t)m * Hc + k0 + c8 * 8);
        }
        __syncthreads();
        // compute chunk t
#pragma unroll
        for (int ks = 0; ks < 4; ++ks) {
            const uint32_t kb = (uint32_t)ks * 32;
            uint32_t ah[2][4], al[2][4];
#pragma unroll
            for (int mf = 0; mf < 2; ++mf) {
                int row = wm * 32 + mf * 16 + (lane & 15);
                uint32_t ao = SWZ128((uint32_t)(row * 128) + kb + ((uint32_t)(lane >> 4) << 4));
                ldsm_x4(ah[mf], sb + XA_HI + ao);
                ldsm_x4(al[mf], sb + XA_LO + ao);
            }
#pragma unroll
            for (int nf2 = 0; nf2 < 4; ++nf2) {
                // paired B load: two nf (8-slot groups) per ldsm_x4
                int slot = wn * 64 + nf2 * 16 + b_nfp * 8 + b_row;
                uint32_t bofs = SWZ128((uint32_t)(slot * 128) + kb + ((uint32_t)b_kh << 4));
                uint32_t bh4[4], bl4[4];
                ldsm_x4(bh4, sb + MB_HI + bofs);
                ldsm_x4(bl4, sb + MB_LO + bofs);
#pragma unroll
                for (int h = 0; h < 2; ++h) {
                    const int nf = nf2 * 2 + h;
#pragma unroll
                    for (int mf = 0; mf < 2; ++mf) {
                        mma_bf16(acc[mf][nf], ah[mf], bh4[2 * h], bh4[2 * h + 1]);
                        mma_bf16(acc[mf][nf], ah[mf], bl4[2 * h], bl4[2 * h + 1]);
                        mma_bf16(acc[mf][nf], al[mf], bh4[2 * h], bh4[2 * h + 1]);
                    }
                }
            }
        }
        __syncthreads();
    }

    // ---------------- softmax over M=256 (cross-warp via s_red) ----------------
    float rmax[2][2], rsum[2][2], inv[2][2];
#pragma unroll
    for (int mf = 0; mf < 2; ++mf)
#pragma unroll
        for (int rh = 0; rh < 2; ++rh) {
            float m = -3.4e38f;
#pragma unroll
            for (int nf = 0; nf < 8; ++nf) {
                m = fmaxf(m, acc[mf][nf][rh * 2]);
                m = fmaxf(m, acc[mf][nf][rh * 2 + 1]);
            }
            m = fmaxf(m, __shfl_xor_sync(0xffffffffu, m, 1));
            m = fmaxf(m, __shfl_xor_sync(0xffffffffu, m, 2));
            rmax[mf][rh] = m;
        }
    if ((lane & 3) == 0) {
#pragma unroll
        for (int mf = 0; mf < 2; ++mf)
#pragma unroll
            for (int rh = 0; rh < 2; ++rh)
                s_red[wn][wm * 32 + mf * 16 + (lane >> 2) + rh * 8] = rmax[mf][rh];
    }
    __syncthreads();
#pragma unroll
    for (int mf = 0; mf < 2; ++mf)
#pragma unroll
        for (int rh = 0; rh < 2; ++rh) {
            int row = wm * 32 + mf * 16 + (lane >> 2) + rh * 8;
            float m = s_red[0][row];
            m = fmaxf(m, s_red[1][row]);
            m = fmaxf(m, s_red[2][row]);
            m = fmaxf(m, s_red[3][row]);
            rmax[mf][rh] = m;
            rsum[mf][rh] = 0.f;
        }
    __syncthreads();
#pragma unroll
    for (int mf = 0; mf < 2; ++mf)
#pragma unroll
        for (int nf = 0; nf < 8; ++nf)
#pragma unroll
            for (int rh = 0; rh < 2; ++rh) {
                float e0 = __expf(acc[mf][nf][rh * 2]     - rmax[mf][rh]);
                float e1 = __expf(acc[mf][nf][rh * 2 + 1] - rmax[mf][rh]);
                acc[mf][nf][rh * 2]     = e0;
                acc[mf][nf][rh * 2 + 1] = e1;
                rsum[mf][rh] += e0 + e1;
            }
#pragma unroll
    for (int mf = 0; mf < 2; ++mf)
#pragma unroll
        for (int rh = 0; rh < 2; ++rh) {
            float s = rsum[mf][rh];
            s += __shfl_xor_sync(0xffffffffu, s, 1);
            s += __shfl_xor_sync(0xffffffffu, s, 2);
            rsum[mf][rh] = s;
        }
    if ((lane & 3) == 0) {
#pragma unroll
        for (int mf = 0; mf < 2; ++mf)
#pragma unroll
            for (int rh = 0; rh < 2; ++rh)
                s_red[wn][wm * 32 + mf * 16 + (lane >> 2) + rh * 8] = rsum[mf][rh];
    }
    __syncthreads();
#pragma unroll
    for (int mf = 0; mf < 2; ++mf)
#pragma unroll
        for (int rh = 0; rh < 2; ++rh) {
            int row = wm * 32 + mf * 16 + (lane >> 2) + rh * 8;
            inv[mf][rh] = 1.0f / (s_red[0][row] + s_red[1][row] +
                                  s_red[2][row] + s_red[3][row]);
        }
    __syncthreads();

    // ---------------- store P (unnormalized exp) as fp16 to smem ----------------
#pragma unroll
    for (int mf = 0; mf < 2; ++mf)
#pragma unroll
        for (int rh = 0; rh < 2; ++rh) {
            int rloc = wm * 32 + mf * 16 + (lane >> 2) + rh * 8;
#pragma unroll
            for (int nf = 0; nf < 8; ++nf) {
                int col = wn * 64 + nf * 8 + (lane & 3) * 2;
                __half2 pv = __floats2half2_rn(acc[mf][nf][rh * 2],
                                               acc[mf][nf][rh * 2 + 1]);
                uint32_t off = SWZ512((uint32_t)(rloc * 512 + col * 2));
                *(uint32_t*)(dsm + P_F16 + off) = *reinterpret_cast<uint32_t*>(&pv);
            }
        }
    __syncthreads();

    // ---------------- phase 2: read = P @ mem (fp16, 1-product) ----------------
    for (int ht = 0; ht < 16; ++ht) {
        const int h0 = ht * 128;
        // stage V tile [128 h x 256 slot] fp16 (single)
#pragma unroll
        for (int it = 0; it < 16; ++it) {
            int idx = it * 256 + tid;
            int r = idx >> 5, c16 = idx & 31;
            uint32_t soff = SWZ512((uint32_t)(r * 512 + c16 * 16));
            *(uint4*)(dsm + V_F16 + soff) =
                *(const uint4*)(g_memT + (size_t)(h0 + r) * Mslots + c16 * 8);
        }
        __syncthreads();

        float o2[2][4][4];
#pragma unroll
        for (int mf = 0; mf < 2; ++mf)
#pragma unroll
            for (int nf = 0; nf < 4; ++nf)
#pragma unroll
                for (int e = 0; e < 4; ++e) o2[mf][nf][e] = 0.f;

#pragma unroll
        for (int ks = 0; ks < 16; ++ks) {
            const uint32_t kb = (uint32_t)ks * 32;
            uint32_t pf[2][4];
#pragma unroll
            for (int mf = 0; mf < 2; ++mf) {
                int row = wm * 32 + mf * 16 + (lane & 15);
                uint32_t ao = SWZ512((uint32_t)(row * 512) + kb + ((uint32_t)(lane >> 4) << 4));
                ldsm_x4(pf[mf], sb + P_F16 + ao);
            }
#pragma unroll
            for (int nf2 = 0; nf2 < 2; ++nf2) {
                // paired V load: two nf (8-h groups) per ldsm_x4
                int hrow = wn * 32 + nf2 * 16 + b_nfp * 8 + b_row;
                uint32_t bofs = SWZ512((uint32_t)(hrow * 512) + kb + ((uint32_t)b_kh << 4));
                uint32_t v4[4];
                ldsm_x4(v4, sb + V_F16 + bofs);
#pragma unroll
                for (int h = 0; h < 2; ++h) {
                    const int nf = nf2 * 2 + h;
#pragma unroll
                    for (int mf = 0; mf < 2; ++mf)
                        mma_f16(o2[mf][nf], pf[mf], v4[2 * h], v4[2 * h + 1]);
                }
            }
        }

        // epilogue: scale by 1/sum, write readm + combined[:, H+...]
#pragma unroll
        for (int mf = 0; mf < 2; ++mf)
#pragma unroll
            for (int rh = 0; rh < 2; ++rh) {
                const size_t row = (size_t)row0 + wm * 32 + mf * 16 + (lane >> 2) + rh * 8;
                const float iv = inv[mf][rh];
#pragma unroll
                for (int nf = 0; nf < 4; ++nf) {
                    int h = h0 + wn * 32 + nf * 8 + (lane & 3) * 2;
                    float2 v = make_float2(o2[mf][nf][rh * 2] * iv,
                                           o2[mf][nf][rh * 2 + 1] * iv);
                    *(float2*)(readm + row * Hc + h) = v;
                    *(float2*)(comb + row * (2 * Hc) + Hc + h) = v;
                }
            }
        __syncthreads();
    }
}

// ======================= write path =======================
__global__ void mean_part_kernel(const float* __restrict__ x) {
    const int sc = blockIdx.x, b = blockIdx.y, tid = threadIdx.x;
    const int SS = Sc / SCHUNKS;
    float acc[8] = {0, 0, 0, 0, 0, 0, 0, 0};
    const float* xp = x + ((size_t)b * Sc + (size_t)sc * SS) * Hc;
    for (int s = 0; s < SS; ++s) {
#pragma unroll
        for (int hh = 0; hh < 8; ++hh)
            acc[hh] += xp[(size_t)s * Hc + tid + hh * 256];
    }
#pragma unroll
    for (int hh = 0; hh < 8; ++hh)
        g_part[((size_t)sc * Bc + b) * Hc + tid + hh * 256] = acc[hh];
}

__global__ void mean_reduce_kernel() {
    const int i = blockIdx.x * 256 + threadIdx.x;
    float s = 0.f;
#pragma unroll
    for (int sc = 0; sc < SCHUNKS; ++sc) s += g_part[(size_t)sc * Bc * Hc + i];
    g_xmean[i] = s * (1.0f / (float)Sc);
}

__global__ void wc_kernel(const float* __restrict__ W, const float* __restrict__ bw) {
    const int gw = (blockIdx.x * blockDim.x + threadIdx.x) >> 5;
    const int lane = threadIdx.x & 31;
    if (gw >= Bc * Hc) return;
    const int b = gw >> 11, i = gw & (Hc - 1);
    const float4* wr = (const float4*)(W + (size_t)i * Hc);
    const float4* xm = (const float4*)(g_xmean + (size_t)b * Hc);
    float s = 0.f;
    for (int k = lane; k < Hc / 4; k += 32) {
        float4 w4 = wr[k], x4 = xm[k];
        s += w4.x * x4.x + w4.y * x4.y + w4.z * x4.z + w4.w * x4.w;
    }
#pragma unroll
    for (int d = 16; d >= 1; d >>= 1) s += __shfl_xor_sync(0xffffffffu, s, d);
    if (lane == 0) g_wc[gw] = s + bw[i];
}

__global__ void newmem_kernel(const float* __restrict__ mem, float* __restrict__ outnm) {
    const size_t idx = (size_t)blockIdx.x * 256 + threadIdx.x;
    const int h4 = (int)(idx & (Hc / 4 - 1));
    const size_t rest = idx >> 9;
    const int m = (int)(rest & (Mslots - 1));
    const int b = (int)(rest >> 8);
    float4 mv = *(const float4*)(mem + (size_t)m * Hc + h4 * 4);
    float4 wv = *(const float4*)(g_wc + (size_t)b * Hc + h4 * 4);
    ((float4*)outnm)[idx] = make_float4(0.9f * mv.x + 0.1f * wv.x, 0.9f * mv.y + 0.1f * wv.y,
                                        0.9f * mv.z + 0.1f * wv.z, 0.9f * mv.w + 0.1f * wv.w);
}

// ======================= launch =======================
extern "C" void kernel_launch(void* const* d_in, const int* in_sizes, int n_in,
                              void* d_out, int out_size) {
    const float* x   = (const float*)d_in[0];
    const float* mem = (const float*)d_in[1];
    const float* W   = (const float*)d_in[2];
    const float* bw  = (const float*)d_in[3];

    float* comb  = (float*)d_out;
    float* readm = comb + (size_t)NROWS * 2 * Hc;
    float* newm  = readm + (size_t)NROWS * Hc;

    cudaFuncSetAttribute(fused_mma_kernel,
                         cudaFuncAttributeMaxDynamicSharedMemorySize, DSMEM);

    prep_mem_kernel<<<(Mslots * Hc) / 256, 256>>>(mem);
    mean_part_kernel<<<dim3(SCHUNKS, Bc), 256>>>(x);
    mean_reduce_kernel<<<(Bc * Hc) / 256, 256>>>();
    wc_kernel<<<(Bc * Hc * 32) / 256, 256>>>(W, bw);
    newmem_kernel<<<(Bc * Mslots * Hc / 4) / 256, 256>>>(mem, newm);
    fused_mma_kernel<<<NROWS / BRr, THREADS, DSMEM>>>(x, comb, readm);
}

// round 11
// speedup vs baseline: 6.4241x; 1.1390x over previous
#include <cuda_runtime.h>
#include <cuda_bf16.h>
#include <cuda_fp16.h>
#include <cstdint>

// ---------------- problem constants ----------------
#define Hc      2048
#define Mslots  256
#define Bc      8
#define Sc      4096
#define NROWS   (Bc * Sc)        // 32768
#define BRr     64               // rows per CTA
#define THREADS 256              // 8 warps; 2 CTAs/SM

// ---------------- dynamic smem layout (96KB) ----------------
// phase 1 (single-buffered k-chunks of 64, fp16 single):
#define XA_F16 0                 // x fp16   [64 x 64k]   8KB
#define MB_F16 8192              // mem fp16 [256 x 64k] 32KB  (end 40KB)
// logits scratch (after phase 1):
#define LG_OFF 0                 // fp32 [64 rows][256]  64KB (stride 256)
#define LG_STR 256
// phase 2:
#define V_F16  0                 // memT fp16 [128h x 256] 64KB
#define P_F16  65536             // P fp16 [64 x 256]      32KB (end 96KB)
#define DSMEM  98304

#define SWZ128(o) ((o) ^ (((o) >> 3) & 0x70))
#define SWZ512(o) ((o) ^ (((o) >> 5) & 0x70))

// ---------------- scratch (__device__ globals) ----------------
__device__ __align__(16) __half g_memF[Mslots * Hc];   // mem fp16 [slot][k]
__device__ __align__(16) __half g_memT[Hc * Mslots];   // memT fp16 [h][slot]
#define SCHUNKS 32
__device__ __align__(16) float g_part[SCHUNKS * Bc * Hc];
__device__ __align__(16) float g_xmean[Bc * Hc];
__device__ __align__(16) float g_wc[Bc * Hc];

// ---------------- helpers ----------------
__device__ __forceinline__ uint32_t smem_u32(const void* p) {
    uint32_t a;
    asm("{ .reg .u64 t; cvta.to.shared.u64 t, %1; cvt.u32.u64 %0, t; }" : "=r"(a) : "l"(p));
    return a;
}
__device__ __forceinline__ void ldsm_x4(uint32_t (&r)[4], uint32_t addr) {
    asm volatile("ldmatrix.sync.aligned.m8n8.x4.shared.b16 {%0,%1,%2,%3}, [%4];"
                 : "=r"(r[0]), "=r"(r[1]), "=r"(r[2]), "=r"(r[3]) : "r"(addr));
}
__device__ __forceinline__ void mma_f16(float (&c)[4], const uint32_t (&a)[4],
                                        uint32_t b0, uint32_t b1) {
    asm volatile(
        "mma.sync.aligned.m16n8k16.row.col.f32.f16.f16.f32 "
        "{%0,%1,%2,%3}, {%4,%5,%6,%7}, {%8,%9}, {%0,%1,%2,%3};"
        : "+f"(c[0]), "+f"(c[1]), "+f"(c[2]), "+f"(c[3])
        : "r"(a[0]), "r"(a[1]), "r"(a[2]), "r"(a[3]), "r"(b0), "r"(b1));
}

// ======================= prep: mem -> fp16 (+transpose) =======================
__global__ void prep_mem_kernel(const float* __restrict__ mem) {
    int i = blockIdx.x * 256 + threadIdx.x;
    int m = i >> 11, h = i & (Hc - 1);
    float v = mem[i];
    __half hv = __float2half_rn(v);
    g_memF[i] = hv;
    g_memT[h * Mslots + m] = hv;
}

// ======================= fused HMMA kernel =======================
extern __shared__ __align__(1024) char dsm[];

__global__ __launch_bounds__(THREADS, 2)
void fused_mma_kernel(const float* __restrict__ x,
                      const float* __restrict__ memf,
                      float* __restrict__ comb,
                      float* __restrict__ readm) {
    __shared__ float s_inv[64];

    const int tid = threadIdx.x;
    const int lane = tid & 31;
    const int wid = tid >> 5;
    const int wm = wid >> 2;             // 0..1 (M position)
    const int wn = wid & 3;              // 0..3 (N position)
    const int row0 = blockIdx.x * BRr;
    const uint32_t sb = smem_u32(dsm);
    // lane decomposition for paired (x4) B loads
    const int b_nfp = (lane >> 4) & 1;
    const int b_kh  = (lane >> 3) & 1;
    const int b_row = lane & 7;

    // ---------------- phase 1: coarse scores = x @ mem^T (fp16, 1 product) ----------------
    float acc[2][8][4];
#pragma unroll
    for (int mf = 0; mf < 2; ++mf)
#pragma unroll
        for (int nf = 0; nf < 8; ++nf)
#pragma unroll
            for (int e = 0; e < 4; ++e) acc[mf][nf][e] = 0.f;

    for (int t = 0; t < 32; ++t) {
        const int k0 = t * 64;
        // stage x chunk (fp16) + free combined copy
#pragma unroll
        for (int it = 0; it < 4; ++it) {
            int idx = it * 256 + tid;
            int r = idx >> 4, c4 = idx & 15;
            float4 v = *(const float4*)(x + (size_t)(row0 + r) * Hc + k0 + c4 * 4);
            *(float4*)(comb + (size_t)(row0 + r) * (2 * Hc) + k0 + c4 * 4) = v;
            __half2 h0 = __floats2half2_rn(v.x, v.y);
            __half2 h1 = __floats2half2_rn(v.z, v.w);
            uint32_t off = SWZ128((uint32_t)(r * 128 + c4 * 8));
            *(uint2*)(dsm + XA_F16 + off) =
                make_uint2(*reinterpret_cast<uint32_t*>(&h0), *reinterpret_cast<uint32_t*>(&h1));
        }
        // stage mem chunk (fp16)
#pragma unroll
        for (int it = 0; it < 8; ++it) {
            int idx = it * 256 + tid;
            int m = idx >> 3, c8 = idx & 7;
            uint32_t off = SWZ128((uint32_t)(m * 128 + c8 * 16));
            *(uint4*)(dsm + MB_F16 + off) = *(const uint4*)(g_memF + (size_t)m * Hc + k0 + c8 * 8);
        }
        __syncthreads();
        // compute chunk
#pragma unroll
        for (int ks = 0; ks < 4; ++ks) {
            const uint32_t kb = (uint32_t)ks * 32;
            uint32_t af[2][4];
#pragma unroll
            for (int mf = 0; mf < 2; ++mf) {
                int row = wm * 32 + mf * 16 + (lane & 15);
                uint32_t ao = SWZ128((uint32_t)(row * 128) + kb + ((uint32_t)(lane >> 4) << 4));
                ldsm_x4(af[mf], sb + XA_F16 + ao);
            }
#pragma unroll
            for (int nf2 = 0; nf2 < 4; ++nf2) {
                int slot = wn * 64 + nf2 * 16 + b_nfp * 8 + b_row;
                uint32_t bofs = SWZ128((uint32_t)(slot * 128) + kb + ((uint32_t)b_kh << 4));
                uint32_t b4[4];
                ldsm_x4(b4, sb + MB_F16 + bofs);
#pragma unroll
                for (int h = 0; h < 2; ++h) {
                    const int nf = nf2 * 2 + h;
#pragma unroll
                    for (int mf = 0; mf < 2; ++mf)
                        mma_f16(acc[mf][nf], af[mf], b4[2 * h], b4[2 * h + 1]);
                }
            }
        }
        __syncthreads();
    }

    // ---------------- dump coarse logits (fp32) to smem ----------------
    float* lg = (float*)(dsm + LG_OFF);
#pragma unroll
    for (int mf = 0; mf < 2; ++mf)
#pragma unroll
        for (int rh = 0; rh < 2; ++rh) {
            int rloc = wm * 32 + mf * 16 + (lane >> 2) + rh * 8;
#pragma unroll
            for (int nf = 0; nf < 8; ++nf) {
                int col = wn * 64 + nf * 8 + (lane & 3) * 2;
                *(float2*)(lg + rloc * LG_STR + col) =
                    make_float2(acc[mf][nf][rh * 2], acc[mf][nf][rh * 2 + 1]);
            }
        }
    __syncthreads();

    // ---------------- refinement + softmax (one warp per 8 rows) ----------------
    for (int rr = 0; rr < 8; ++rr) {
        const int rl = wid * 8 + rr;
        float* Lrow = lg + rl * LG_STR;
        // coarse max
        float cm = -3.4e38f;
#pragma unroll
        for (int i = 0; i < 8; ++i) cm = fmaxf(cm, Lrow[lane + i * 32]);
#pragma unroll
        for (int d = 16; d >= 1; d >>= 1)
            cm = fmaxf(cm, __shfl_xor_sync(0xffffffffu, cm, d));
        const float thr = cm - 10.0f;
        // exact recompute of candidate slots
#pragma unroll
        for (int i = 0; i < 8; ++i) {
            int slot = lane + i * 32;
            bool cand = Lrow[slot] > thr;
            unsigned mask = __ballot_sync(0xffffffffu, cand);
            while (mask) {
                int src = __ffs(mask) - 1;
                mask &= mask - 1;
                int s2 = src + i * 32;
                const float4* xp = (const float4*)(x + (size_t)(row0 + rl) * Hc);
                const float4* mp = (const float4*)(memf + (size_t)s2 * Hc);
                float d = 0.f;
                for (int k = lane; k < Hc / 4; k += 32) {
                    float4 a = xp[k], b = mp[k];
                    d += a.x * b.x + a.y * b.y + a.z * b.z + a.w * b.w;
                }
#pragma unroll
                for (int dd = 16; dd >= 1; dd >>= 1)
                    d += __shfl_xor_sync(0xffffffffu, d, dd);
                if (lane == 0) Lrow[s2] = d;
            }
        }
        __syncwarp();
        // exact max over refined logits
        float m2 = -3.4e38f;
#pragma unroll
        for (int i = 0; i < 8; ++i) m2 = fmaxf(m2, Lrow[lane + i * 32]);
#pragma unroll
        for (int d = 16; d >= 1; d >>= 1)
            m2 = fmaxf(m2, __shfl_xor_sync(0xffffffffu, m2, d));
        // exp + sum + write unnormalized P (fp16)
        float s = 0.f;
#pragma unroll
        for (int i = 0; i < 4; ++i) {
            int p = lane + i * 32;                 // half2 pair index, 0..127
            float e0 = __expf(Lrow[2 * p]     - m2);
            float e1 = __expf(Lrow[2 * p + 1] - m2);
            s += e0 + e1;
            __half2 pv = __floats2half2_rn(e0, e1);
            uint32_t off = SWZ512((uint32_t)(rl * 512 + p * 4));
            *(uint32_t*)(dsm + P_F16 + off) = *reinterpret_cast<uint32_t*>(&pv);
        }
#pragma unroll
        for (int d = 16; d >= 1; d >>= 1)
            s += __shfl_xor_sync(0xffffffffu, s, d);
        if (lane == 0) s_inv[rl] = 1.0f / s;
    }
    __syncthreads();

    // ---------------- phase 2: read = P @ mem (fp16, 1 product) ----------------
    for (int ht = 0; ht < 16; ++ht) {
        const int h0 = ht * 128;
        // stage V tile [128 h x 256 slot] fp16
#pragma unroll
        for (int it = 0; it < 16; ++it) {
            int idx = it * 256 + tid;
            int r = idx >> 5, c16 = idx & 31;
            uint32_t soff = SWZ512((uint32_t)(r * 512 + c16 * 16));
            *(uint4*)(dsm + V_F16 + soff) =
                *(const uint4*)(g_memT + (size_t)(h0 + r) * Mslots + c16 * 8);
        }
        __syncthreads();

        float o2[2][4][4];
#pragma unroll
        for (int mf = 0; mf < 2; ++mf)
#pragma unroll
            for (int nf = 0; nf < 4; ++nf)
#pragma unroll
                for (int e = 0; e < 4; ++e) o2[mf][nf][e] = 0.f;

#pragma unroll
        for (int ks = 0; ks < 16; ++ks) {
            const uint32_t kb = (uint32_t)ks * 32;
            uint32_t pf[2][4];
#pragma unroll
            for (int mf = 0; mf < 2; ++mf) {
                int row = wm * 32 + mf * 16 + (lane & 15);
                uint32_t ao = SWZ512((uint32_t)(row * 512) + kb + ((uint32_t)(lane >> 4) << 4));
                ldsm_x4(pf[mf], sb + P_F16 + ao);
            }
#pragma unroll
            for (int nf2 = 0; nf2 < 2; ++nf2) {
                int hrow = wn * 32 + nf2 * 16 + b_nfp * 8 + b_row;
                uint32_t bofs = SWZ512((uint32_t)(hrow * 512) + kb + ((uint32_t)b_kh << 4));
                uint32_t v4[4];
                ldsm_x4(v4, sb + V_F16 + bofs);
#pragma unroll
                for (int h = 0; h < 2; ++h) {
                    const int nf = nf2 * 2 + h;
#pragma unroll
                    for (int mf = 0; mf < 2; ++mf)
                        mma_f16(o2[mf][nf], pf[mf], v4[2 * h], v4[2 * h + 1]);
                }
            }
        }

        // epilogue: scale by 1/sum, write readm + combined[:, H+...]
#pragma unroll
        for (int mf = 0; mf < 2; ++mf)
#pragma unroll
            for (int rh = 0; rh < 2; ++rh) {
                const int rloc = wm * 32 + mf * 16 + (lane >> 2) + rh * 8;
                const size_t row = (size_t)row0 + rloc;
                const float iv = s_inv[rloc];
#pragma unroll
                for (int nf = 0; nf < 4; ++nf) {
                    int h = h0 + wn * 32 + nf * 8 + (lane & 3) * 2;
                    float2 v = make_float2(o2[mf][nf][rh * 2] * iv,
                                           o2[mf][nf][rh * 2 + 1] * iv);
                    *(float2*)(readm + row * Hc + h) = v;
                    *(float2*)(comb + row * (2 * Hc) + Hc + h) = v;
                }
            }
        __syncthreads();
    }
}

// ======================= write path =======================
__global__ void mean_part_kernel(const float* __restrict__ x) {
    const int sc = blockIdx.x, b = blockIdx.y, tid = threadIdx.x;
    const int SS = Sc / SCHUNKS;
    float acc[8] = {0, 0, 0, 0, 0, 0, 0, 0};
    const float* xp = x + ((size_t)b * Sc + (size_t)sc * SS) * Hc;
    for (int s = 0; s < SS; ++s) {
#pragma unroll
        for (int hh = 0; hh < 8; ++hh)
            acc[hh] += xp[(size_t)s * Hc + tid + hh * 256];
    }
#pragma unroll
    for (int hh = 0; hh < 8; ++hh)
        g_part[((size_t)sc * Bc + b) * Hc + tid + hh * 256] = acc[hh];
}

__global__ void mean_reduce_kernel() {
    const int i = blockIdx.x * 256 + threadIdx.x;
    float s = 0.f;
#pragma unroll
    for (int sc = 0; sc < SCHUNKS; ++sc) s += g_part[(size_t)sc * Bc * Hc + i];
    g_xmean[i] = s * (1.0f / (float)Sc);
}

__global__ void wc_kernel(const float* __restrict__ W, const float* __restrict__ bw) {
    const int gw = (blockIdx.x * blockDim.x + threadIdx.x) >> 5;
    const int lane = threadIdx.x & 31;
    if (gw >= Bc * Hc) return;
    const int b = gw >> 11, i = gw & (Hc - 1);
    const float4* wr = (const float4*)(W + (size_t)i * Hc);
    const float4* xm = (const float4*)(g_xmean + (size_t)b * Hc);
    float s = 0.f;
    for (int k = lane; k < Hc / 4; k += 32) {
        float4 w4 = wr[k], x4 = xm[k];
        s += w4.x * x4.x + w4.y * x4.y + w4.z * x4.z + w4.w * x4.w;
    }
#pragma unroll
    for (int d = 16; d >= 1; d >>= 1) s += __shfl_xor_sync(0xffffffffu, s, d);
    if (lane == 0) g_wc[gw] = s + bw[i];
}

__global__ void newmem_kernel(const float* __restrict__ mem, float* __restrict__ outnm) {
    const size_t idx = (size_t)blockIdx.x * 256 + threadIdx.x;
    const int h4 = (int)(idx & (Hc / 4 - 1));
    const size_t rest = idx >> 9;
    const int m = (int)(rest & (Mslots - 1));
    const int b = (int)(rest >> 8);
    float4 mv = *(const float4*)(mem + (size_t)m * Hc + h4 * 4);
    float4 wv = *(const float4*)(g_wc + (size_t)b * Hc + h4 * 4);
    ((float4*)outnm)[idx] = make_float4(0.9f * mv.x + 0.1f * wv.x, 0.9f * mv.y + 0.1f * wv.y,
                                        0.9f * mv.z + 0.1f * wv.z, 0.9f * mv.w + 0.1f * wv.w);
}

// ======================= launch =======================
extern "C" void kernel_launch(void* const* d_in, const int* in_sizes, int n_in,
                              void* d_out, int out_size) {
    const float* x   = (const float*)d_in[0];
    const float* mem = (const float*)d_in[1];
    const float* W   = (const float*)d_in[2];
    const float* bw  = (const float*)d_in[3];

    float* comb  = (float*)d_out;
    float* readm = comb + (size_t)NROWS * 2 * Hc;
    float* newm  = readm + (size_t)NROWS * Hc;

    cudaFuncSetAttribute(fused_mma_kernel,
                         cudaFuncAttributeMaxDynamicSharedMemorySize, DSMEM);

    prep_mem_kernel<<<(Mslots * Hc) / 256, 256>>>(mem);
    mean_part_kernel<<<dim3(SCHUNKS, Bc), 256>>>(x);
    mean_reduce_kernel<<<(Bc * Hc) / 256, 256>>>();
    wc_kernel<<<(Bc * Hc * 32) / 256, 256>>>(W, bw);
    newmem_kernel<<<(Bc * Mslots * Hc / 4) / 256, 256>>>(mem, newm);
    fused_mma_kernel<<<NROWS / BRr, THREADS, DSMEM>>>(x, mem, comb, readm);
}

// round 12
// speedup vs baseline: 7.7450x; 1.2056x over previous
#include <cuda_runtime.h>
#include <cuda_fp16.h>
#include <cstdint>

// ---------------- problem constants ----------------
#define Hc      2048
#define Mslots  256
#define Bc      8
#define Sc      4096
#define NROWS   (Bc * Sc)        // 32768
#define BRr     64               // rows per CTA
#define THREADS 256              // 8 warps; 2 CTAs/SM

// ---------------- dynamic smem layout (64KB) ----------------
// phase 1 (single-buffered k-chunks of 64, fp16 single):
#define XA_F16 0                 // x fp16   [64 x 64k]   8KB
#define MB_F16 8192              // mem fp16 [256 x 64k] 32KB  (end 40KB)
// logits scratch (after phase 1; reuses allocation):
#define LG_OFF 0                 // fp32 [64 rows][256]  64KB
#define LG_STR 256
#define DSMEM  65536

#define SWZ128(o) ((o) ^ (((o) >> 3) & 0x70))

// ---------------- scratch (__device__ globals) ----------------
__device__ __align__(16) __half g_memF[Mslots * Hc];   // mem fp16 [slot][k]
#define SCHUNKS 32
__device__ __align__(16) float g_part[SCHUNKS * Bc * Hc];
__device__ __align__(16) float g_xmean[Bc * Hc];
__device__ __align__(16) float g_wc[Bc * Hc];

// ---------------- helpers ----------------
__device__ __forceinline__ uint32_t smem_u32(const void* p) {
    uint32_t a;
    asm("{ .reg .u64 t; cvta.to.shared.u64 t, %1; cvt.u32.u64 %0, t; }" : "=r"(a) : "l"(p));
    return a;
}
__device__ __forceinline__ void ldsm_x4(uint32_t (&r)[4], uint32_t addr) {
    asm volatile("ldmatrix.sync.aligned.m8n8.x4.shared.b16 {%0,%1,%2,%3}, [%4];"
                 : "=r"(r[0]), "=r"(r[1]), "=r"(r[2]), "=r"(r[3]) : "r"(addr));
}
__device__ __forceinline__ void mma_f16(float (&c)[4], const uint32_t (&a)[4],
                                        uint32_t b0, uint32_t b1) {
    asm volatile(
        "mma.sync.aligned.m16n8k16.row.col.f32.f16.f16.f32 "
        "{%0,%1,%2,%3}, {%4,%5,%6,%7}, {%8,%9}, {%0,%1,%2,%3};"
        : "+f"(c[0]), "+f"(c[1]), "+f"(c[2]), "+f"(c[3])
        : "r"(a[0]), "r"(a[1]), "r"(a[2]), "r"(a[3]), "r"(b0), "r"(b1));
}

// ======================= prep: mem -> fp16 =======================
__global__ void prep_mem_kernel(const float* __restrict__ mem) {
    int i = blockIdx.x * 256 + threadIdx.x;
    g_memF[i] = __float2half_rn(mem[i]);
}

// ======================= fused kernel =======================
extern __shared__ __align__(1024) char dsm[];

__global__ __launch_bounds__(THREADS, 2)
void fused_mma_kernel(const float* __restrict__ x,
                      const float* __restrict__ memf,
                      float* __restrict__ comb,
                      float* __restrict__ readm) {
    const int tid = threadIdx.x;
    const int lane = tid & 31;
    const int wid = tid >> 5;
    const int wm = wid >> 2;             // 0..1 (M position)
    const int wn = wid & 3;              // 0..3 (N position)
    const int row0 = blockIdx.x * BRr;
    const uint32_t sb = smem_u32(dsm);
    const int b_nfp = (lane >> 4) & 1;
    const int b_kh  = (lane >> 3) & 1;
    const int b_row = lane & 7;

    // ---------------- phase 1: coarse scores = x @ mem^T (fp16, 1 product) ----------------
    float acc[2][8][4];
#pragma unroll
    for (int mf = 0; mf < 2; ++mf)
#pragma unroll
        for (int nf = 0; nf < 8; ++nf)
#pragma unroll
            for (int e = 0; e < 4; ++e) acc[mf][nf][e] = 0.f;

    for (int t = 0; t < 32; ++t) {
        const int k0 = t * 64;
        // stage x chunk (fp16) + free combined copy
#pragma unroll
        for (int it = 0; it < 4; ++it) {
            int idx = it * 256 + tid;
            int r = idx >> 4, c4 = idx & 15;
            float4 v = *(const float4*)(x + (size_t)(row0 + r) * Hc + k0 + c4 * 4);
            *(float4*)(comb + (size_t)(row0 + r) * (2 * Hc) + k0 + c4 * 4) = v;
            __half2 h0 = __floats2half2_rn(v.x, v.y);
            __half2 h1 = __floats2half2_rn(v.z, v.w);
            uint32_t off = SWZ128((uint32_t)(r * 128 + c4 * 8));
            *(uint2*)(dsm + XA_F16 + off) =
                make_uint2(*reinterpret_cast<uint32_t*>(&h0), *reinterpret_cast<uint32_t*>(&h1));
        }
        // stage mem chunk (fp16)
#pragma unroll
        for (int it = 0; it < 8; ++it) {
            int idx = it * 256 + tid;
            int m = idx >> 3, c8 = idx & 7;
            uint32_t off = SWZ128((uint32_t)(m * 128 + c8 * 16));
            *(uint4*)(dsm + MB_F16 + off) = *(const uint4*)(g_memF + (size_t)m * Hc + k0 + c8 * 8);
        }
        __syncthreads();
        // compute chunk
#pragma unroll
        for (int ks = 0; ks < 4; ++ks) {
            const uint32_t kb = (uint32_t)ks * 32;
            uint32_t af[2][4];
#pragma unroll
            for (int mf = 0; mf < 2; ++mf) {
                int row = wm * 32 + mf * 16 + (lane & 15);
                uint32_t ao = SWZ128((uint32_t)(row * 128) + kb + ((uint32_t)(lane >> 4) << 4));
                ldsm_x4(af[mf], sb + XA_F16 + ao);
            }
#pragma unroll
            for (int nf2 = 0; nf2 < 4; ++nf2) {
                int slot = wn * 64 + nf2 * 16 + b_nfp * 8 + b_row;
                uint32_t bofs = SWZ128((uint32_t)(slot * 128) + kb + ((uint32_t)b_kh << 4));
                uint32_t b4[4];
                ldsm_x4(b4, sb + MB_F16 + bofs);
#pragma unroll
                for (int h = 0; h < 2; ++h) {
                    const int nf = nf2 * 2 + h;
#pragma unroll
                    for (int mf = 0; mf < 2; ++mf)
                        mma_f16(acc[mf][nf], af[mf], b4[2 * h], b4[2 * h + 1]);
                }
            }
        }
        __syncthreads();
    }

    // ---------------- dump coarse logits (fp32) to smem ----------------
    float* lg = (float*)(dsm + LG_OFF);
#pragma unroll
    for (int mf = 0; mf < 2; ++mf)
#pragma unroll
        for (int rh = 0; rh < 2; ++rh) {
            int rloc = wm * 32 + mf * 16 + (lane >> 2) + rh * 8;
#pragma unroll
            for (int nf = 0; nf < 8; ++nf) {
                int col = wn * 64 + nf * 8 + (lane & 3) * 2;
                *(float2*)(lg + rloc * LG_STR + col) =
                    make_float2(acc[mf][nf][rh * 2], acc[mf][nf][rh * 2 + 1]);
            }
        }
    __syncthreads();

    // ---------------- per-row: refine -> softmax -> sparse-exact output ----------------
    // one warp per 8 rows
    for (int rr = 0; rr < 8; ++rr) {
        const int rl = wid * 8 + rr;
        float* Lrow = lg + rl * LG_STR;

        // coarse max
        float cm = -3.4e38f;
#pragma unroll
        for (int i = 0; i < 8; ++i) cm = fmaxf(cm, Lrow[lane + i * 32]);
#pragma unroll
        for (int d = 16; d >= 1; d >>= 1)
            cm = fmaxf(cm, __shfl_xor_sync(0xffffffffu, cm, d));
        const float thr = cm - 14.0f;

        // exact recompute of candidate slots (fp32 from global)
#pragma unroll
        for (int i = 0; i < 8; ++i) {
            int slot = lane + i * 32;
            bool cand = Lrow[slot] > thr;
            unsigned mask = __ballot_sync(0xffffffffu, cand);
            while (mask) {
                int src = __ffs(mask) - 1;
                mask &= mask - 1;
                int s2 = src + i * 32;
                const float4* xp = (const float4*)(x + (size_t)(row0 + rl) * Hc);
                const float4* mp = (const float4*)(memf + (size_t)s2 * Hc);
                float d = 0.f;
                for (int k = lane; k < Hc / 4; k += 32) {
                    float4 a = xp[k], b = mp[k];
                    d += a.x * b.x + a.y * b.y + a.z * b.z + a.w * b.w;
                }
#pragma unroll
                for (int dd = 16; dd >= 1; dd >>= 1)
                    d += __shfl_xor_sync(0xffffffffu, d, dd);
                if (lane == 0) Lrow[s2] = d;
            }
        }
        __syncwarp();

        // exact max + sum over all 256 (refined where it matters)
        float m2 = -3.4e38f;
#pragma unroll
        for (int i = 0; i < 8; ++i) m2 = fmaxf(m2, Lrow[lane + i * 32]);
#pragma unroll
        for (int d = 16; d >= 1; d >>= 1)
            m2 = fmaxf(m2, __shfl_xor_sync(0xffffffffu, m2, d));
        float s = 0.f;
#pragma unroll
        for (int i = 0; i < 8; ++i) s += __expf(Lrow[lane + i * 32] - m2);
#pragma unroll
        for (int d = 16; d >= 1; d >>= 1)
            s += __shfl_xor_sync(0xffffffffu, s, d);
        const float inv = 1.0f / s;
        const float thr2 = m2 - 14.0f;

        // output: read[rl][:] = sum_{cand} w_c * mem[c][:]  (fp32 exact, 4 h-chunks)
        float* rp = readm + (size_t)(row0 + rl) * Hc;
        float* cp = comb + (size_t)(row0 + rl) * (2 * Hc) + Hc;
#pragma unroll
        for (int hc = 0; hc < 4; ++hc) {
            float4 out[4];
#pragma unroll
            for (int j = 0; j < 4; ++j) out[j] = make_float4(0.f, 0.f, 0.f, 0.f);
#pragma unroll
            for (int i = 0; i < 8; ++i) {
                bool cand = Lrow[lane + i * 32] > thr2;
                unsigned mask = __ballot_sync(0xffffffffu, cand);
                while (mask) {
                    int src = __ffs(mask) - 1;
                    mask &= mask - 1;
                    int s2 = src + i * 32;
                    float w = __expf(Lrow[s2] - m2) * inv;
                    const float4* mp = (const float4*)(memf + (size_t)s2 * Hc) + hc * 128;
#pragma unroll
                    for (int j = 0; j < 4; ++j) {
                        float4 mv = mp[lane + j * 32];
                        out[j].x += w * mv.x;
                        out[j].y += w * mv.y;
                        out[j].z += w * mv.z;
                        out[j].w += w * mv.w;
                    }
                }
            }
#pragma unroll
            for (int j = 0; j < 4; ++j) {
                int h4 = hc * 128 + lane + j * 32;   // float4 index within row
                *(float4*)(rp + h4 * 4) = out[j];
                *(float4*)(cp + h4 * 4) = out[j];
            }
        }
    }
}

// ======================= write path =======================
__global__ void mean_part_kernel(const float* __restrict__ x) {
    const int sc = blockIdx.x, b = blockIdx.y, tid = threadIdx.x;
    const int SS = Sc / SCHUNKS;
    float acc[8] = {0, 0, 0, 0, 0, 0, 0, 0};
    const float* xp = x + ((size_t)b * Sc + (size_t)sc * SS) * Hc;
    for (int s = 0; s < SS; ++s) {
#pragma unroll
        for (int hh = 0; hh < 8; ++hh)
            acc[hh] += xp[(size_t)s * Hc + tid + hh * 256];
    }
#pragma unroll
    for (int hh = 0; hh < 8; ++hh)
        g_part[((size_t)sc * Bc + b) * Hc + tid + hh * 256] = acc[hh];
}

__global__ void mean_reduce_kernel() {
    const int i = blockIdx.x * 256 + threadIdx.x;
    float s = 0.f;
#pragma unroll
    for (int sc = 0; sc < SCHUNKS; ++sc) s += g_part[(size_t)sc * Bc * Hc + i];
    g_xmean[i] = s * (1.0f / (float)Sc);
}

__global__ void wc_kernel(const float* __restrict__ W, const float* __restrict__ bw) {
    const int gw = (blockIdx.x * blockDim.x + threadIdx.x) >> 5;
    const int lane = threadIdx.x & 31;
    if (gw >= Bc * Hc) return;
    const int b = gw >> 11, i = gw & (Hc - 1);
    const float4* wr = (const float4*)(W + (size_t)i * Hc);
    const float4* xm = (const float4*)(g_xmean + (size_t)b * Hc);
    float s = 0.f;
    for (int k = lane; k < Hc / 4; k += 32) {
        float4 w4 = wr[k], x4 = xm[k];
        s += w4.x * x4.x + w4.y * x4.y + w4.z * x4.z + w4.w * x4.w;
    }
#pragma unroll
    for (int d = 16; d >= 1; d >>= 1) s += __shfl_xor_sync(0xffffffffu, s, d);
    if (lane == 0) g_wc[gw] = s + bw[i];
}

__global__ void newmem_kernel(const float* __restrict__ mem, float* __restrict__ outnm) {
    const size_t idx = (size_t)blockIdx.x * 256 + threadIdx.x;
    const int h4 = (int)(idx & (Hc / 4 - 1));
    const size_t rest = idx >> 9;
    const int m = (int)(rest & (Mslots - 1));
    const int b = (int)(rest >> 8);
    float4 mv = *(const float4*)(mem + (size_t)m * Hc + h4 * 4);
    float4 wv = *(const float4*)(g_wc + (size_t)b * Hc + h4 * 4);
    ((float4*)outnm)[idx] = make_float4(0.9f * mv.x + 0.1f * wv.x, 0.9f * mv.y + 0.1f * wv.y,
                                        0.9f * mv.z + 0.1f * wv.z, 0.9f * mv.w + 0.1f * wv.w);
}

// ======================= launch =======================
extern "C" void kernel_launch(void* const* d_in, const int* in_sizes, int n_in,
                              void* d_out, int out_size) {
    const float* x   = (const float*)d_in[0];
    const float* mem = (const float*)d_in[1];
    const float* W   = (const float*)d_in[2];
    const float* bw  = (const float*)d_in[3];

    float* comb  = (float*)d_out;
    float* readm = comb + (size_t)NROWS * 2 * Hc;
    float* newm  = readm + (size_t)NROWS * Hc;

    cudaFuncSetAttribute(fused_mma_kernel,
                         cudaFuncAttributeMaxDynamicSharedMemorySize, DSMEM);

    prep_mem_kernel<<<(Mslots * Hc) / 256, 256>>>(mem);
    mean_part_kernel<<<dim3(SCHUNKS, Bc), 256>>>(x);
    mean_reduce_kernel<<<(Bc * Hc) / 256, 256>>>();
    wc_kernel<<<(Bc * Hc * 32) / 256, 256>>>(W, bw);
    newmem_kernel<<<(Bc * Mslots * Hc / 4) / 256, 256>>>(mem, newm);
    fused_mma_kernel<<<NROWS / BRr, THREADS, DSMEM>>>(x, mem, comb, readm);
}